// round 1
// baseline (speedup 1.0000x reference)
#include <cuda_runtime.h>
#include <math.h>

#define NN   16384
#define EE   32768
#define DIM  64
#define NGR  512

// ---------------- device scratch (no allocations allowed) ----------------
__device__ float g_out[NN * DIM];          // node state (out == h throughout)
__device__ float g_H[EE * 128];            // edge MLP hidden
__device__ float g_We[EE * 4096];          // per-edge 64x64 weight matrices (512MB)
__device__ float g_agg[NN * DIM];          // scatter accumulator
__device__ float g_deg[NN];                // in-degree (float)
__device__ int   g_ptr[NGR + 1];           // graph offsets (batch is sorted)

__device__ __forceinline__ float sigm(float x) { return 1.0f / (1.0f + expf(-x)); }

// ---------------- init: zero deg + agg ----------------
__global__ void k_init() {
    int i = blockIdx.x * 256 + threadIdx.x;
    if (i < NN) g_deg[i] = 0.0f;
    if (i < NN * DIM) g_agg[i] = 0.0f;
}

// ---------------- lin0: out = relu(x @ lin0_w + b), x [N,29] ----------------
__global__ void __launch_bounds__(256) k_lin0(const float* __restrict__ x,
                                              const float* __restrict__ w,
                                              const float* __restrict__ b) {
    __shared__ float ws[29 * 64];
    __shared__ float xs[4][32];
    int tid = threadIdx.x;
    int d = tid & 63, gq = tid >> 6;
    for (int i = tid; i < 29 * 64; i += 256) ws[i] = w[i];
    int n = blockIdx.x * 4 + gq;
    if (d < 29) xs[gq][d] = x[n * 29 + d];
    __syncthreads();
    float acc = b[d];
#pragma unroll
    for (int j = 0; j < 29; j++) acc += xs[gq][j] * ws[j * 64 + d];
    g_out[n * 64 + d] = fmaxf(acc, 0.0f);
}

// ---------------- graph offsets: lower_bound over sorted batch ----------------
__global__ void k_ptr(const int* __restrict__ batch) {
    int g = blockIdx.x * blockDim.x + threadIdx.x;
    if (g > NGR) return;
    if (g == NGR) { g_ptr[g] = NN; return; }
    int lo = 0, hi = NN;
    while (lo < hi) { int mid = (lo + hi) >> 1; if (batch[mid] < g) lo = mid + 1; else hi = mid; }
    g_ptr[g] = lo;
}

// ---------------- degree ----------------
__global__ void k_deg(const int* __restrict__ dstv) {
    int e = blockIdx.x * 256 + threadIdx.x;
    if (e < EE) atomicAdd(&g_deg[dstv[e]], 1.0f);
}

// ---------------- edge MLP layer 1: H = relu(ea @ W1 + b1), [E,6]->[E,128] ----------------
__global__ void __launch_bounds__(256) k_mlp1(const float* __restrict__ ea,
                                              const float* __restrict__ w1,
                                              const float* __restrict__ b1) {
    __shared__ float ws[6 * 128];
    __shared__ float bs[128];
    __shared__ float es[2][8];
    int tid = threadIdx.x;
    int k = tid & 127, gq = tid >> 7;
    for (int i = tid; i < 768; i += 256) ws[i] = w1[i];
    if (tid < 128) bs[tid] = b1[tid];
    int e = blockIdx.x * 2 + gq;
    if (k < 6) es[gq][k] = ea[e * 6 + k];
    __syncthreads();
    float acc = bs[k];
#pragma unroll
    for (int j = 0; j < 6; j++) acc += es[gq][j] * ws[j * 128 + k];
    g_H[e * 128 + k] = fmaxf(acc, 0.0f);
}

// ---------------- We GEMM: [32768,128] @ [128,4096] + b2 -> g_We ----------------
// 128x128 tile, BK=16, 256 threads, 8x8 microtile.
__global__ void __launch_bounds__(256) k_gemm_We(const float* __restrict__ B,
                                                 const float* __restrict__ bias) {
    const int K = 128, Nc = 4096;
    __shared__ float As[16][128];
    __shared__ float Bs[16][128];
    int tid = threadIdx.x;
    int bx = blockIdx.x, by = blockIdx.y;
    int tx = tid % 16, ty = tid / 16;
    int rowBase = by * 128, colBase = bx * 128;
    float acc[8][8];
#pragma unroll
    for (int i = 0; i < 8; i++)
#pragma unroll
        for (int j = 0; j < 8; j++) acc[i][j] = 0.0f;

    for (int kk = 0; kk < K; kk += 16) {
#pragma unroll
        for (int h = 0; h < 2; h++) {
            int r = (tid >> 2) + h * 64;
            int kq = (tid & 3) * 4;
            float4 v = *(const float4*)&g_H[(size_t)(rowBase + r) * K + kk + kq];
            As[kq + 0][r] = v.x; As[kq + 1][r] = v.y; As[kq + 2][r] = v.z; As[kq + 3][r] = v.w;
        }
#pragma unroll
        for (int h = 0; h < 2; h++) {
            int r = (tid >> 5) + h * 8;
            int cq = (tid & 31) * 4;
            float4 v = *(const float4*)&B[(size_t)(kk + r) * Nc + colBase + cq];
            *(float4*)&Bs[r][cq] = v;
        }
        __syncthreads();
#pragma unroll
        for (int k = 0; k < 16; k++) {
            float ar[8], br[8];
#pragma unroll
            for (int i = 0; i < 8; i++) ar[i] = As[k][ty * 8 + i];
#pragma unroll
            for (int j = 0; j < 8; j++) br[j] = Bs[k][tx * 8 + j];
#pragma unroll
            for (int i = 0; i < 8; i++)
#pragma unroll
                for (int j = 0; j < 8; j++) acc[i][j] += ar[i] * br[j];
        }
        __syncthreads();
    }
#pragma unroll
    for (int i = 0; i < 8; i++) {
        int r = rowBase + ty * 8 + i;
#pragma unroll
        for (int j = 0; j < 8; j += 4) {
            int c = colBase + tx * 8 + j;
            float4 v;
            v.x = acc[i][j + 0] + bias[c + 0];
            v.y = acc[i][j + 1] + bias[c + 1];
            v.z = acc[i][j + 2] + bias[c + 2];
            v.w = acc[i][j + 3] + bias[c + 3];
            *(float4*)&g_We[(size_t)r * Nc + c] = v;
        }
    }
}

// ---------------- message + scatter: agg[dst] += out[src] @ We_e ----------------
__global__ void __launch_bounds__(256) k_msg(const int* __restrict__ src,
                                             const int* __restrict__ dstv) {
    int tid = threadIdx.x;
    int o = tid & 63, gq = tid >> 6;
    int e = blockIdx.x * 4 + gq;
    __shared__ float os[4][64];
    int s = src[e];
    os[gq][o] = g_out[s * 64 + o];
    __syncthreads();
    const float* w = g_We + (size_t)e * 4096 + o;
    float acc = 0.0f;
#pragma unroll 8
    for (int i = 0; i < 64; i++) acc += os[gq][i] * __ldg(&w[i * 64]);
    atomicAdd(&g_agg[dstv[e] * 64 + o], acc);
}

// ---------------- node update: conv + relu + GRU (h == out), zeroes agg ----------------
// 256 threads = 4 groups x 64 dims, 2 nodes per group-slot, block handles 64 nodes.
__global__ void __launch_bounds__(256) k_node(const float* __restrict__ conv_root,
                                              const float* __restrict__ conv_bias,
                                              const float* __restrict__ wih,
                                              const float* __restrict__ whh,
                                              const float* __restrict__ bihg,
                                              const float* __restrict__ bhhg) {
    extern __shared__ float sm[];
    float* conv = sm;                 // 4096
    float* wihT = conv + 4096;        // 12288 : [i*192 + j]
    float* whhT = wihT + 12288;       // 12288
    float* cb   = whhT + 12288;       // 64
    float* bih  = cb + 64;            // 192
    float* bhh  = bih + 192;          // 192
    float* outs = bhh + 192;          // 8*64
    float* ms   = outs + 512;         // 8*64

    int tid = threadIdx.x;
    for (int idx = tid; idx < 4096; idx += 256) conv[idx] = conv_root[idx];
    for (int idx = tid; idx < 12288; idx += 256) {
        int j = idx / 64, i = idx % 64;
        wihT[i * 192 + j] = wih[idx];
        whhT[i * 192 + j] = whh[idx];
    }
    if (tid < 64) cb[tid] = conv_bias[tid];
    if (tid < 192) { bih[tid] = bihg[tid]; bhh[tid] = bhhg[tid]; }
    __syncthreads();

    int d = tid & 63, gq = tid >> 6;
    int blockStart = blockIdx.x * 64;

    for (int pass = 0; pass < 8; pass++) {
        __syncthreads();
        int n0 = blockStart + pass * 8 + gq * 2;
        int n1 = n0 + 1;
        outs[(gq * 2 + 0) * 64 + d] = g_out[n0 * 64 + d];
        outs[(gq * 2 + 1) * 64 + d] = g_out[n1 * 64 + d];
        __syncthreads();

        float di0 = 1.0f / fmaxf(g_deg[n0], 1.0f);
        float di1 = 1.0f / fmaxf(g_deg[n1], 1.0f);
        float a0 = g_agg[n0 * 64 + d] * di0 + cb[d];
        float a1 = g_agg[n1 * 64 + d] * di1 + cb[d];
        g_agg[n0 * 64 + d] = 0.0f;   // zero for next iteration's scatter
        g_agg[n1 * 64 + d] = 0.0f;

        const float* o0 = &outs[(gq * 2) * 64];
        const float* o1 = o0 + 64;
#pragma unroll 8
        for (int i = 0; i < 64; i++) {
            float c = conv[i * 64 + d];
            a0 += o0[i] * c;
            a1 += o1[i] * c;
        }
        float m0 = fmaxf(a0, 0.0f), m1 = fmaxf(a1, 0.0f);
        ms[(gq * 2) * 64 + d] = m0;
        ms[(gq * 2 + 1) * 64 + d] = m1;
        __syncthreads();

        float gr0 = bih[d], gz0 = bih[64 + d], gn0 = bih[128 + d];
        float gr1 = gr0,    gz1 = gz0,         gn1 = gn0;
        float hr0 = bhh[d], hz0 = bhh[64 + d], hn0 = bhh[128 + d];
        float hr1 = hr0,    hz1 = hz0,         hn1 = hn0;
        const float* mm0 = &ms[(gq * 2) * 64];
        const float* mm1 = mm0 + 64;
#pragma unroll 4
        for (int i = 0; i < 64; i++) {
            float w0 = wihT[i * 192 + d], w1 = wihT[i * 192 + 64 + d], w2 = wihT[i * 192 + 128 + d];
            float u0 = whhT[i * 192 + d], u1 = whhT[i * 192 + 64 + d], u2 = whhT[i * 192 + 128 + d];
            float mi0 = mm0[i], mi1 = mm1[i], oi0 = o0[i], oi1 = o1[i];
            gr0 += mi0 * w0; gz0 += mi0 * w1; gn0 += mi0 * w2;
            gr1 += mi1 * w0; gz1 += mi1 * w1; gn1 += mi1 * w2;
            hr0 += oi0 * u0; hz0 += oi0 * u1; hn0 += oi0 * u2;
            hr1 += oi1 * u0; hz1 += oi1 * u1; hn1 += oi1 * u2;
        }
        {
            float r = sigm(gr0 + hr0);
            float z = sigm(gz0 + hz0);
            float nv = tanhf(gn0 + r * hn0);
            g_out[n0 * 64 + d] = (1.0f - z) * nv + z * o0[d];
        }
        {
            float r = sigm(gr1 + hr1);
            float z = sigm(gz1 + hz1);
            float nv = tanhf(gn1 + r * hn1);
            g_out[n1 * 64 + d] = (1.0f - z) * nv + z * o1[d];
        }
    }
}

// ---------------- Set2Set (3 steps) + lin1/lin2 head; one block per graph ----------------
__global__ void __launch_bounds__(256) k_s2s(const float* __restrict__ wih,
                                             const float* __restrict__ whh,
                                             const float* __restrict__ bih,
                                             const float* __restrict__ bhh,
                                             const float* __restrict__ l1w,
                                             const float* __restrict__ l1b,
                                             const float* __restrict__ l2w,
                                             const float* __restrict__ l2b,
                                             float* __restrict__ y) {
    int g = blockIdx.x, tid = threadIdx.x;
    __shared__ float qstar[128], hl[64], cl[64], gsm[256], a_sm[256], red[256], rvp[256];
    __shared__ float s_inv;
    if (tid < 128) qstar[tid] = 0.0f;
    if (tid < 64) { hl[tid] = 0.0f; cl[tid] = 0.0f; }
    int start = g_ptr[g], cnt = g_ptr[g + 1] - start;
    __syncthreads();
    int d = tid & 63, gq = tid >> 6;

    for (int step = 0; step < 3; step++) {
        // ---- LSTM (thread = gate row) ----
        float acc = bih[tid] + bhh[tid];
        const float* wr = wih + tid * 128;
#pragma unroll 8
        for (int i = 0; i < 128; i++) acc += qstar[i] * wr[i];
        const float* ur = whh + tid * 64;
#pragma unroll 8
        for (int i = 0; i < 64; i++) acc += hl[i] * ur[i];
        gsm[tid] = acc;
        __syncthreads();
        if (tid < 64) {
            float ii = sigm(gsm[tid]);
            float ff = sigm(gsm[64 + tid]);
            float gg = tanhf(gsm[128 + tid]);
            float oo = sigm(gsm[192 + tid]);
            float c = ff * cl[tid] + ii * gg;
            cl[tid] = c;
            hl[tid] = oo * tanhf(c);
        }
        __syncthreads();

        // ---- attention pass 1: segment max ----
        float lmax = -3.0e38f;
        for (int j = tid; j < cnt; j += 256) {
            const float* orow = g_out + (size_t)(start + j) * 64;
            float e = 0.0f;
#pragma unroll 8
            for (int k2 = 0; k2 < 64; k2++) e += orow[k2] * hl[k2];
            lmax = fmaxf(lmax, e);
        }
        red[tid] = lmax;
        __syncthreads();
        for (int s = 128; s; s >>= 1) { if (tid < s) red[tid] = fmaxf(red[tid], red[tid + s]); __syncthreads(); }
        float emax = red[0];
        __syncthreads();

        // ---- attention pass 2: sum + weighted readout ----
        float rv = 0.0f, asum = 0.0f;
        for (int base = 0; base < cnt; base += 256) {
            int chunk = min(256, cnt - base);
            if (tid < chunk) {
                const float* orow = g_out + (size_t)(start + base + tid) * 64;
                float e = 0.0f;
#pragma unroll 8
                for (int k2 = 0; k2 < 64; k2++) e += orow[k2] * hl[k2];
                a_sm[tid] = expf(e - emax);
            }
            __syncthreads();
            for (int j = gq; j < chunk; j += 4) {
                float a = a_sm[j];
                rv += a * g_out[(size_t)(start + base + j) * 64 + d];
                if (d == 0) asum += a;
            }
            __syncthreads();
        }
        rvp[tid] = rv;
        red[tid] = (d == 0) ? asum : 0.0f;
        __syncthreads();
        if (tid == 0) s_inv = 1.0f / (red[0] + red[64] + red[128] + red[192] + 1e-16f);
        __syncthreads();
        if (tid < 64) {
            float rvt = rvp[tid] + rvp[64 + tid] + rvp[128 + tid] + rvp[192 + tid];
            qstar[tid] = hl[tid];
            qstar[64 + tid] = rvt * s_inv;
        }
        __syncthreads();
    }

    // ---- head: y = relu(q_star @ l1w + l1b) @ l2w + l2b ----
    float t = 0.0f;
    if (tid < 64) {
        float acc = l1b[tid];
#pragma unroll 8
        for (int i = 0; i < 128; i++) acc += qstar[i] * l1w[i * 64 + tid];
        t = fmaxf(acc, 0.0f) * l2w[tid];
    }
    red[tid] = (tid < 64) ? t : 0.0f;
    __syncthreads();
    for (int s = 128; s; s >>= 1) { if (tid < s) red[tid] += red[tid + s]; __syncthreads(); }
    if (tid == 0) y[g] = red[0] + l2b[0];
}

// ---------------- host launcher ----------------
extern "C" void kernel_launch(void* const* d_in, const int* in_sizes, int n_in,
                              void* d_out, int out_size) {
    const float* x        = (const float*)d_in[0];
    const int*   ei       = (const int*)  d_in[1];
    const float* ea       = (const float*)d_in[2];
    const int*   batch    = (const int*)  d_in[3];
    const float* lin0_w   = (const float*)d_in[4];
    const float* lin0_b   = (const float*)d_in[5];
    const float* nn_w1    = (const float*)d_in[6];
    const float* nn_b1    = (const float*)d_in[7];
    const float* nn_w2    = (const float*)d_in[8];
    const float* nn_b2    = (const float*)d_in[9];
    const float* conv_root= (const float*)d_in[10];
    const float* conv_bias= (const float*)d_in[11];
    const float* gru_wih  = (const float*)d_in[12];
    const float* gru_whh  = (const float*)d_in[13];
    const float* gru_bih  = (const float*)d_in[14];
    const float* gru_bhh  = (const float*)d_in[15];
    const float* lstm_wih = (const float*)d_in[16];
    const float* lstm_whh = (const float*)d_in[17];
    const float* lstm_bih = (const float*)d_in[18];
    const float* lstm_bhh = (const float*)d_in[19];
    const float* lin1_w   = (const float*)d_in[20];
    const float* lin1_b   = (const float*)d_in[21];
    const float* lin2_w   = (const float*)d_in[22];
    const float* lin2_b   = (const float*)d_in[23];
    float* y = (float*)d_out;

    const int* src  = ei;
    const int* dstv = ei + EE;

    const int NODE_SMEM = 30144 * 4;
    cudaFuncSetAttribute(k_node, cudaFuncAttributeMaxDynamicSharedMemorySize, NODE_SMEM);

    k_init<<<NN * DIM / 256, 256>>>();
    k_lin0<<<NN / 4, 256>>>(x, lin0_w, lin0_b);
    k_ptr<<<3, 256>>>(batch);
    k_deg<<<EE / 256, 256>>>(dstv);
    k_mlp1<<<EE / 2, 256>>>(ea, nn_w1, nn_b1);
    k_gemm_We<<<dim3(32, 256), 256>>>(nn_w2, nn_b2);

    for (int it = 0; it < 6; it++) {
        k_msg<<<EE / 4, 256>>>(src, dstv);
        k_node<<<NN / 64, 256, NODE_SMEM>>>(conv_root, conv_bias,
                                            gru_wih, gru_whh, gru_bih, gru_bhh);
    }

    k_s2s<<<NGR, 256>>>(lstm_wih, lstm_whh, lstm_bih, lstm_bhh,
                        lin1_w, lin1_b, lin2_w, lin2_b, y);
}

// round 2
// speedup vs baseline: 1.3234x; 1.3234x over previous
#include <cuda_runtime.h>
#include <cuda_bf16.h>
#include <cuda_fp16.h>
#include <math.h>

#define NN   16384
#define EE   32768
#define DIM  64
#define NGR  512

// ---------------- device scratch ----------------
__device__ float g_out[NN * DIM];                 // node state
__device__ float g_H[EE * 128];                   // edge MLP hidden (fp32)
__device__ __nv_bfloat16 g_Ah[EE * 384];          // split A' = [Ahi|Alo|Ahi]
__device__ __nv_bfloat16 g_Bh[384 * 4096];        // split B' = [Bhi;Bhi;Blo]
__device__ __half g_We_h[(size_t)EE * 4096];      // per-edge 64x64 weights, fp16 (256MB)
__device__ float g_agg[NN * DIM];
__device__ float g_deg[NN];
__device__ int   g_ptr[NGR + 1];

__device__ __forceinline__ float sigm(float x) { return 1.0f / (1.0f + expf(-x)); }
__device__ __forceinline__ unsigned smem_u32(const void* p) {
    return (unsigned)__cvta_generic_to_shared(p);
}

// ---------------- init ----------------
__global__ void k_init() {
    int i = blockIdx.x * 256 + threadIdx.x;
    if (i < NN) g_deg[i] = 0.0f;
    if (i < NN * DIM) g_agg[i] = 0.0f;
}

// ---------------- lin0 ----------------
__global__ void __launch_bounds__(256) k_lin0(const float* __restrict__ x,
                                              const float* __restrict__ w,
                                              const float* __restrict__ b) {
    __shared__ float ws[29 * 64];
    __shared__ float xs[4][32];
    int tid = threadIdx.x;
    int d = tid & 63, gq = tid >> 6;
    for (int i = tid; i < 29 * 64; i += 256) ws[i] = w[i];
    int n = blockIdx.x * 4 + gq;
    if (d < 29) xs[gq][d] = x[n * 29 + d];
    __syncthreads();
    float acc = b[d];
#pragma unroll
    for (int j = 0; j < 29; j++) acc += xs[gq][j] * ws[j * 64 + d];
    g_out[n * 64 + d] = fmaxf(acc, 0.0f);
}

// ---------------- graph offsets ----------------
__global__ void k_ptr(const int* __restrict__ batch) {
    int g = blockIdx.x * blockDim.x + threadIdx.x;
    if (g > NGR) return;
    if (g == NGR) { g_ptr[g] = NN; return; }
    int lo = 0, hi = NN;
    while (lo < hi) { int mid = (lo + hi) >> 1; if (batch[mid] < g) lo = mid + 1; else hi = mid; }
    g_ptr[g] = lo;
}

// ---------------- degree ----------------
__global__ void k_deg(const int* __restrict__ dstv) {
    int e = blockIdx.x * 256 + threadIdx.x;
    if (e < EE) atomicAdd(&g_deg[dstv[e]], 1.0f);
}

// ---------------- edge MLP layer 1 ----------------
__global__ void __launch_bounds__(256) k_mlp1(const float* __restrict__ ea,
                                              const float* __restrict__ w1,
                                              const float* __restrict__ b1) {
    __shared__ float ws[6 * 128];
    __shared__ float bs[128];
    __shared__ float es[2][8];
    int tid = threadIdx.x;
    int k = tid & 127, gq = tid >> 7;
    for (int i = tid; i < 768; i += 256) ws[i] = w1[i];
    if (tid < 128) bs[tid] = b1[tid];
    int e = blockIdx.x * 2 + gq;
    if (k < 6) es[gq][k] = ea[e * 6 + k];
    __syncthreads();
    float acc = bs[k];
#pragma unroll
    for (int j = 0; j < 6; j++) acc += es[gq][j] * ws[j * 128 + k];
    g_H[e * 128 + k] = fmaxf(acc, 0.0f);
}

// ---------------- split A: g_H [E,128] fp32 -> g_Ah [E,384] bf16 ----------------
__global__ void k_splitA() {
    int idx = blockIdx.x * 256 + threadIdx.x;      // over E*128
    int r = idx >> 7, c = idx & 127;
    float x = g_H[idx];
    __nv_bfloat16 hi = __float2bfloat16_rn(x);
    __nv_bfloat16 lo = __float2bfloat16_rn(x - __bfloat162float(hi));
    __nv_bfloat16* row = g_Ah + (size_t)r * 384;
    row[c] = hi; row[128 + c] = lo; row[256 + c] = hi;
}

// ---------------- split B: nn_w2 [128,4096] -> g_Bh [384,4096] ----------------
__global__ void k_splitB(const float* __restrict__ w2) {
    int idx = blockIdx.x * 256 + threadIdx.x;      // over 128*4096
    int r = idx >> 12, c = idx & 4095;
    float x = w2[idx];
    __nv_bfloat16 hi = __float2bfloat16_rn(x);
    __nv_bfloat16 lo = __float2bfloat16_rn(x - __bfloat162float(hi));
    g_Bh[(size_t)r * 4096 + c] = hi;
    g_Bh[(size_t)(r + 128) * 4096 + c] = hi;
    g_Bh[(size_t)(r + 256) * 4096 + c] = lo;
}

// ---------------- bf16 tensor-core GEMM: [32768,384]@[384,4096] + bias -> fp16 ----------------
// 128x128 tile, BK=32, 256 threads (8 warps, 4x2), cp.async double buffer.
__global__ void __launch_bounds__(256) k_gemm_bf16(const float* __restrict__ bias) {
    const int KT = 12;                 // 384/32
    __shared__ __nv_bfloat16 As[2][128][40];   // padded: 80B row = 5x16B (odd)
    __shared__ __nv_bfloat16 Bs[2][32][136];   // padded: 272B row = 17x16B (odd)
    __shared__ float biass[128];

    int tid = threadIdx.x;
    int lane = tid & 31, wid = tid >> 5;
    int warp_m = wid & 3, warp_n = wid >> 2;
    int bn = blockIdx.x * 128, bm = blockIdx.y * 128;

    if (tid < 128) biass[tid] = bias[bn + tid];

    float acc[2][8][4];
#pragma unroll
    for (int i = 0; i < 2; i++)
#pragma unroll
        for (int j = 0; j < 8; j++)
#pragma unroll
            for (int r = 0; r < 4; r++) acc[i][j][r] = 0.0f;

    // gmem addresses for async loads
    int arow = tid >> 2, acol = (tid & 3) * 8;           // A: 64 rows/pass, 2 passes
    int brow = tid >> 4, bcol = (tid & 15) * 8;          // B: 16 rows/pass, 2 passes

    auto issue = [&](int kt, int buf) {
        const __nv_bfloat16* agp = g_Ah + (size_t)(bm + arow) * 384 + kt * 32 + acol;
#pragma unroll
        for (int h = 0; h < 2; h++) {
            unsigned s = smem_u32(&As[buf][arow + h * 64][acol]);
            asm volatile("cp.async.cg.shared.global [%0], [%1], 16;\n" :: "r"(s),
                         "l"(agp + (size_t)h * 64 * 384));
        }
        const __nv_bfloat16* bgp = g_Bh + (size_t)(kt * 32 + brow) * 4096 + bn + bcol;
#pragma unroll
        for (int h = 0; h < 2; h++) {
            unsigned s = smem_u32(&Bs[buf][brow + h * 16][bcol]);
            asm volatile("cp.async.cg.shared.global [%0], [%1], 16;\n" :: "r"(s),
                         "l"(bgp + (size_t)h * 16 * 4096));
        }
        asm volatile("cp.async.commit_group;\n");
    };

    issue(0, 0);

    for (int kt = 0; kt < KT; kt++) {
        int buf = kt & 1;
        asm volatile("cp.async.wait_group 0;\n");
        __syncthreads();
        if (kt + 1 < KT) issue(kt + 1, (kt + 1) & 1);

#pragma unroll
        for (int ks = 0; ks < 2; ks++) {
            unsigned a[2][4];
#pragma unroll
            for (int mt = 0; mt < 2; mt++) {
                unsigned addr = smem_u32(&As[buf][warp_m * 32 + mt * 16 + (lane & 15)]
                                            [ks * 16 + (lane >> 4) * 8]);
                asm volatile("ldmatrix.sync.aligned.m8n8.x4.shared.b16 {%0,%1,%2,%3}, [%4];\n"
                             : "=r"(a[mt][0]), "=r"(a[mt][1]), "=r"(a[mt][2]), "=r"(a[mt][3])
                             : "r"(addr));
            }
            unsigned b[4][4];
#pragma unroll
            for (int p = 0; p < 4; p++) {
                unsigned addr = smem_u32(&Bs[buf][ks * 16 + (lane & 15)]
                                            [warp_n * 64 + p * 16 + (lane >> 4) * 8]);
                asm volatile("ldmatrix.sync.aligned.m8n8.x4.trans.shared.b16 {%0,%1,%2,%3}, [%4];\n"
                             : "=r"(b[p][0]), "=r"(b[p][1]), "=r"(b[p][2]), "=r"(b[p][3])
                             : "r"(addr));
            }
#pragma unroll
            for (int mt = 0; mt < 2; mt++)
#pragma unroll
                for (int nt = 0; nt < 8; nt++) {
                    unsigned b0 = b[nt >> 1][(nt & 1) * 2];
                    unsigned b1 = b[nt >> 1][(nt & 1) * 2 + 1];
                    asm volatile(
                        "mma.sync.aligned.m16n8k16.row.col.f32.bf16.bf16.f32 "
                        "{%0,%1,%2,%3}, {%4,%5,%6,%7}, {%8,%9}, {%0,%1,%2,%3};\n"
                        : "+f"(acc[mt][nt][0]), "+f"(acc[mt][nt][1]),
                          "+f"(acc[mt][nt][2]), "+f"(acc[mt][nt][3])
                        : "r"(a[mt][0]), "r"(a[mt][1]), "r"(a[mt][2]), "r"(a[mt][3]),
                          "r"(b0), "r"(b1));
                }
        }
        __syncthreads();
    }

    // epilogue: bias + fp16 store
#pragma unroll
    for (int mt = 0; mt < 2; mt++) {
        int row0 = bm + warp_m * 32 + mt * 16 + (lane >> 2);
#pragma unroll
        for (int nt = 0; nt < 8; nt++) {
            int colL = warp_n * 64 + nt * 8 + (lane & 3) * 2;
            int col = bn + colL;
            float b0 = biass[colL], b1 = biass[colL + 1];
            __half2 v0 = __floats2half2_rn(acc[mt][nt][0] + b0, acc[mt][nt][1] + b1);
            __half2 v1 = __floats2half2_rn(acc[mt][nt][2] + b0, acc[mt][nt][3] + b1);
            *(__half2*)&g_We_h[(size_t)row0 * 4096 + col] = v0;
            *(__half2*)&g_We_h[(size_t)(row0 + 8) * 4096 + col] = v1;
        }
    }
}

// ---------------- message + scatter (fp16 We) ----------------
__global__ void __launch_bounds__(256) k_msg(const int* __restrict__ src,
                                             const int* __restrict__ dstv) {
    int tid = threadIdx.x;
    int o = tid & 63, gq = tid >> 6;
    int e = blockIdx.x * 4 + gq;
    __shared__ float os[4][64];
    int s = src[e];
    os[gq][o] = g_out[s * 64 + o];
    __syncthreads();
    const __half* w = g_We_h + (size_t)e * 4096 + o;
    float acc = 0.0f;
#pragma unroll 8
    for (int i = 0; i < 64; i++) acc += os[gq][i] * __half2float(__ldg(&w[i * 64]));
    atomicAdd(&g_agg[dstv[e] * 64 + o], acc);
}

// ---------------- node update: conv + relu + GRU, zeroes agg ----------------
__global__ void __launch_bounds__(256) k_node(const float* __restrict__ conv_root,
                                              const float* __restrict__ conv_bias,
                                              const float* __restrict__ wih,
                                              const float* __restrict__ whh,
                                              const float* __restrict__ bihg,
                                              const float* __restrict__ bhhg) {
    extern __shared__ float sm[];
    float* conv = sm;
    float* wihT = conv + 4096;
    float* whhT = wihT + 12288;
    float* cb   = whhT + 12288;
    float* bih  = cb + 64;
    float* bhh  = bih + 192;
    float* outs = bhh + 192;
    float* ms   = outs + 512;

    int tid = threadIdx.x;
    for (int idx = tid; idx < 4096; idx += 256) conv[idx] = conv_root[idx];
    for (int idx = tid; idx < 12288; idx += 256) {
        int j = idx / 64, i = idx % 64;
        wihT[i * 192 + j] = wih[idx];
        whhT[i * 192 + j] = whh[idx];
    }
    if (tid < 64) cb[tid] = conv_bias[tid];
    if (tid < 192) { bih[tid] = bihg[tid]; bhh[tid] = bhhg[tid]; }
    __syncthreads();

    int d = tid & 63, gq = tid >> 6;
    int blockStart = blockIdx.x * 64;

    for (int pass = 0; pass < 8; pass++) {
        __syncthreads();
        int n0 = blockStart + pass * 8 + gq * 2;
        int n1 = n0 + 1;
        outs[(gq * 2 + 0) * 64 + d] = g_out[n0 * 64 + d];
        outs[(gq * 2 + 1) * 64 + d] = g_out[n1 * 64 + d];
        __syncthreads();

        float di0 = 1.0f / fmaxf(g_deg[n0], 1.0f);
        float di1 = 1.0f / fmaxf(g_deg[n1], 1.0f);
        float a0 = g_agg[n0 * 64 + d] * di0 + cb[d];
        float a1 = g_agg[n1 * 64 + d] * di1 + cb[d];
        g_agg[n0 * 64 + d] = 0.0f;
        g_agg[n1 * 64 + d] = 0.0f;

        const float* o0 = &outs[(gq * 2) * 64];
        const float* o1 = o0 + 64;
#pragma unroll 8
        for (int i = 0; i < 64; i++) {
            float c = conv[i * 64 + d];
            a0 += o0[i] * c;
            a1 += o1[i] * c;
        }
        float m0 = fmaxf(a0, 0.0f), m1 = fmaxf(a1, 0.0f);
        ms[(gq * 2) * 64 + d] = m0;
        ms[(gq * 2 + 1) * 64 + d] = m1;
        __syncthreads();

        float gr0 = bih[d], gz0 = bih[64 + d], gn0 = bih[128 + d];
        float gr1 = gr0,    gz1 = gz0,         gn1 = gn0;
        float hr0 = bhh[d], hz0 = bhh[64 + d], hn0 = bhh[128 + d];
        float hr1 = hr0,    hz1 = hz0,         hn1 = hn0;
        const float* mm0 = &ms[(gq * 2) * 64];
        const float* mm1 = mm0 + 64;
#pragma unroll 4
        for (int i = 0; i < 64; i++) {
            float w0 = wihT[i * 192 + d], w1 = wihT[i * 192 + 64 + d], w2 = wihT[i * 192 + 128 + d];
            float u0 = whhT[i * 192 + d], u1 = whhT[i * 192 + 64 + d], u2 = whhT[i * 192 + 128 + d];
            float mi0 = mm0[i], mi1 = mm1[i], oi0 = o0[i], oi1 = o1[i];
            gr0 += mi0 * w0; gz0 += mi0 * w1; gn0 += mi0 * w2;
            gr1 += mi1 * w0; gz1 += mi1 * w1; gn1 += mi1 * w2;
            hr0 += oi0 * u0; hz0 += oi0 * u1; hn0 += oi0 * u2;
            hr1 += oi1 * u0; hz1 += oi1 * u1; hn1 += oi1 * u2;
        }
        {
            float r = sigm(gr0 + hr0);
            float z = sigm(gz0 + hz0);
            float nv = tanhf(gn0 + r * hn0);
            g_out[n0 * 64 + d] = (1.0f - z) * nv + z * o0[d];
        }
        {
            float r = sigm(gr1 + hr1);
            float z = sigm(gz1 + hz1);
            float nv = tanhf(gn1 + r * hn1);
            g_out[n1 * 64 + d] = (1.0f - z) * nv + z * o1[d];
        }
    }
}

// ---------------- Set2Set + head ----------------
__global__ void __launch_bounds__(256) k_s2s(const float* __restrict__ wih,
                                             const float* __restrict__ whh,
                                             const float* __restrict__ bih,
                                             const float* __restrict__ bhh,
                                             const float* __restrict__ l1w,
                                             const float* __restrict__ l1b,
                                             const float* __restrict__ l2w,
                                             const float* __restrict__ l2b,
                                             float* __restrict__ y) {
    int g = blockIdx.x, tid = threadIdx.x;
    __shared__ float qstar[128], hl[64], cl[64], gsm[256], a_sm[256], red[256], rvp[256];
    __shared__ float s_inv;
    if (tid < 128) qstar[tid] = 0.0f;
    if (tid < 64) { hl[tid] = 0.0f; cl[tid] = 0.0f; }
    int start = g_ptr[g], cnt = g_ptr[g + 1] - start;
    __syncthreads();
    int d = tid & 63, gq = tid >> 6;

    for (int step = 0; step < 3; step++) {
        float acc = bih[tid] + bhh[tid];
        const float* wr = wih + tid * 128;
#pragma unroll 8
        for (int i = 0; i < 128; i++) acc += qstar[i] * wr[i];
        const float* ur = whh + tid * 64;
#pragma unroll 8
        for (int i = 0; i < 64; i++) acc += hl[i] * ur[i];
        gsm[tid] = acc;
        __syncthreads();
        if (tid < 64) {
            float ii = sigm(gsm[tid]);
            float ff = sigm(gsm[64 + tid]);
            float gg = tanhf(gsm[128 + tid]);
            float oo = sigm(gsm[192 + tid]);
            float c = ff * cl[tid] + ii * gg;
            cl[tid] = c;
            hl[tid] = oo * tanhf(c);
        }
        __syncthreads();

        float lmax = -3.0e38f;
        for (int j = tid; j < cnt; j += 256) {
            const float* orow = g_out + (size_t)(start + j) * 64;
            float e = 0.0f;
#pragma unroll 8
            for (int k2 = 0; k2 < 64; k2++) e += orow[k2] * hl[k2];
            lmax = fmaxf(lmax, e);
        }
        red[tid] = lmax;
        __syncthreads();
        for (int s = 128; s; s >>= 1) { if (tid < s) red[tid] = fmaxf(red[tid], red[tid + s]); __syncthreads(); }
        float emax = red[0];
        __syncthreads();

        float rv = 0.0f, asum = 0.0f;
        for (int base = 0; base < cnt; base += 256) {
            int chunk = min(256, cnt - base);
            if (tid < chunk) {
                const float* orow = g_out + (size_t)(start + base + tid) * 64;
                float e = 0.0f;
#pragma unroll 8
                for (int k2 = 0; k2 < 64; k2++) e += orow[k2] * hl[k2];
                a_sm[tid] = expf(e - emax);
            }
            __syncthreads();
            for (int j = gq; j < chunk; j += 4) {
                float a = a_sm[j];
                rv += a * g_out[(size_t)(start + base + j) * 64 + d];
                if (d == 0) asum += a;
            }
            __syncthreads();
        }
        rvp[tid] = rv;
        red[tid] = (d == 0) ? asum : 0.0f;
        __syncthreads();
        if (tid == 0) s_inv = 1.0f / (red[0] + red[64] + red[128] + red[192] + 1e-16f);
        __syncthreads();
        if (tid < 64) {
            float rvt = rvp[tid] + rvp[64 + tid] + rvp[128 + tid] + rvp[192 + tid];
            qstar[tid] = hl[tid];
            qstar[64 + tid] = rvt * s_inv;
        }
        __syncthreads();
    }

    float t = 0.0f;
    if (tid < 64) {
        float acc = l1b[tid];
#pragma unroll 8
        for (int i = 0; i < 128; i++) acc += qstar[i] * l1w[i * 64 + tid];
        t = fmaxf(acc, 0.0f) * l2w[tid];
    }
    red[tid] = (tid < 64) ? t : 0.0f;
    __syncthreads();
    for (int s = 128; s; s >>= 1) { if (tid < s) red[tid] += red[tid + s]; __syncthreads(); }
    if (tid == 0) y[g] = red[0] + l2b[0];
}

// ---------------- host launcher ----------------
extern "C" void kernel_launch(void* const* d_in, const int* in_sizes, int n_in,
                              void* d_out, int out_size) {
    const float* x        = (const float*)d_in[0];
    const int*   ei       = (const int*)  d_in[1];
    const float* ea       = (const float*)d_in[2];
    const int*   batch    = (const int*)  d_in[3];
    const float* lin0_w   = (const float*)d_in[4];
    const float* lin0_b   = (const float*)d_in[5];
    const float* nn_w1    = (const float*)d_in[6];
    const float* nn_b1    = (const float*)d_in[7];
    const float* nn_w2    = (const float*)d_in[8];
    const float* nn_b2    = (const float*)d_in[9];
    const float* conv_root= (const float*)d_in[10];
    const float* conv_bias= (const float*)d_in[11];
    const float* gru_wih  = (const float*)d_in[12];
    const float* gru_whh  = (const float*)d_in[13];
    const float* gru_bih  = (const float*)d_in[14];
    const float* gru_bhh  = (const float*)d_in[15];
    const float* lstm_wih = (const float*)d_in[16];
    const float* lstm_whh = (const float*)d_in[17];
    const float* lstm_bih = (const float*)d_in[18];
    const float* lstm_bhh = (const float*)d_in[19];
    const float* lin1_w   = (const float*)d_in[20];
    const float* lin1_b   = (const float*)d_in[21];
    const float* lin2_w   = (const float*)d_in[22];
    const float* lin2_b   = (const float*)d_in[23];
    float* y = (float*)d_out;

    const int* src  = ei;
    const int* dstv = ei + EE;

    const int NODE_SMEM = 30144 * 4;
    cudaFuncSetAttribute(k_node, cudaFuncAttributeMaxDynamicSharedMemorySize, NODE_SMEM);

    k_init<<<NN * DIM / 256, 256>>>();
    k_lin0<<<NN / 4, 256>>>(x, lin0_w, lin0_b);
    k_ptr<<<3, 256>>>(batch);
    k_deg<<<EE / 256, 256>>>(dstv);
    k_mlp1<<<EE / 2, 256>>>(ea, nn_w1, nn_b1);
    k_splitA<<<EE * 128 / 256, 256>>>();
    k_splitB<<<128 * 4096 / 256, 256>>>(nn_w2);
    k_gemm_bf16<<<dim3(32, 256), 256>>>(nn_b2);

    for (int it = 0; it < 6; it++) {
        k_msg<<<EE / 4, 256>>>(src, dstv);
        k_node<<<NN / 64, 256, NODE_SMEM>>>(conv_root, conv_bias,
                                            gru_wih, gru_whh, gru_bih, gru_bhh);
    }

    k_s2s<<<NGR, 256>>>(lstm_wih, lstm_whh, lstm_bih, lstm_bhh,
                        lin1_w, lin1_b, lin2_w, lin2_b, y);
}

// round 4
// speedup vs baseline: 1.5533x; 1.1737x over previous
#include <cuda_runtime.h>
#include <cuda_fp16.h>
#include <math.h>
#include <stdint.h>

#define NN   16384
#define EE   32768
#define DIM  64
#define NGR  512

// ---------------- device scratch ----------------
__device__ float g_out[NN * DIM];                 // node state
__device__ float g_H[EE * 128];                   // edge MLP hidden (fp32)
__device__ __half g_Af[EE * 128];                 // A in fp16 [E,128]
__device__ __half g_Bf[128 * 4096];               // B in fp16 [128,4096]
__device__ __half g_We_h[(size_t)EE * 4096];      // per-edge 64x64 weights, fp16 (256MB)
__device__ float g_agg[NN * DIM];
__device__ float g_deg[NN];
__device__ int   g_ptr[NGR + 1];

__device__ __forceinline__ float sigm(float x) { return 1.0f / (1.0f + expf(-x)); }
__device__ __forceinline__ unsigned smem_u32(const void* p) {
    return (unsigned)__cvta_generic_to_shared(p);
}

// ---------------- init ----------------
__global__ void k_init() {
    int i = blockIdx.x * 256 + threadIdx.x;
    if (i < NN) g_deg[i] = 0.0f;
    if (i < NN * DIM) g_agg[i] = 0.0f;
}

// ---------------- lin0 ----------------
__global__ void __launch_bounds__(256) k_lin0(const float* __restrict__ x,
                                              const float* __restrict__ w,
                                              const float* __restrict__ b) {
    __shared__ float ws[29 * 64];
    __shared__ float xs[4][32];
    int tid = threadIdx.x;
    int d = tid & 63, gq = tid >> 6;
    for (int i = tid; i < 29 * 64; i += 256) ws[i] = w[i];
    int n = blockIdx.x * 4 + gq;
    if (d < 29) xs[gq][d] = x[n * 29 + d];
    __syncthreads();
    float acc = b[d];
#pragma unroll
    for (int j = 0; j < 29; j++) acc += xs[gq][j] * ws[j * 64 + d];
    g_out[n * 64 + d] = fmaxf(acc, 0.0f);
}

// ---------------- graph offsets ----------------
__global__ void k_ptr(const int* __restrict__ batch) {
    int g = blockIdx.x * blockDim.x + threadIdx.x;
    if (g > NGR) return;
    if (g == NGR) { g_ptr[g] = NN; return; }
    int lo = 0, hi = NN;
    while (lo < hi) { int mid = (lo + hi) >> 1; if (batch[mid] < g) lo = mid + 1; else hi = mid; }
    g_ptr[g] = lo;
}

// ---------------- degree ----------------
__global__ void k_deg(const int* __restrict__ dstv) {
    int e = blockIdx.x * 256 + threadIdx.x;
    if (e < EE) atomicAdd(&g_deg[dstv[e]], 1.0f);
}

// ---------------- edge MLP layer 1 ----------------
__global__ void __launch_bounds__(256) k_mlp1(const float* __restrict__ ea,
                                              const float* __restrict__ w1,
                                              const float* __restrict__ b1) {
    __shared__ float ws[6 * 128];
    __shared__ float bs[128];
    __shared__ float es[2][8];
    int tid = threadIdx.x;
    int k = tid & 127, gq = tid >> 7;
    for (int i = tid; i < 768; i += 256) ws[i] = w1[i];
    if (tid < 128) bs[tid] = b1[tid];
    int e = blockIdx.x * 2 + gq;
    if (k < 6) es[gq][k] = ea[e * 6 + k];
    __syncthreads();
    float acc = bs[k];
#pragma unroll
    for (int j = 0; j < 6; j++) acc += es[gq][j] * ws[j * 128 + k];
    g_H[e * 128 + k] = fmaxf(acc, 0.0f);
}

// ---------------- convert A: g_H fp32 -> g_Af fp16 ----------------
__global__ void k_cvtA() {
    int i = blockIdx.x * 256 + threadIdx.x;     // over E*128/2
    float2 v = *(const float2*)&g_H[i * 2];
    *(__half2*)&g_Af[i * 2] = __floats2half2_rn(v.x, v.y);
}

// ---------------- convert B: nn_w2 fp32 -> g_Bf fp16 ----------------
__global__ void k_cvtB(const float* __restrict__ w2) {
    int i = blockIdx.x * 256 + threadIdx.x;     // over 128*4096/2
    float2 v = *(const float2*)&w2[i * 2];
    *(__half2*)&g_Bf[i * 2] = __floats2half2_rn(v.x, v.y);
}

// ---------------- fp16 tensor-core GEMM: [32768,128]@[128,4096] + bias -> fp16 ----------------
// 128x128 tile, BK=32, KT=4, 3-stage cp.async, 256 threads (8 warps 4x2).
// Dynamic smem: A stages @ s*10240 (128x40 halfs), B stages @ 30720+s*8704 (32x136 halfs),
// bias @ 56832. Epilogue stage[128][66] u32 aliases bytes [0,33792).
__global__ void __launch_bounds__(256) k_gemm_f16(const float* __restrict__ bias) {
    extern __shared__ __align__(16) char smraw[];
    __half* Asm = (__half*)smraw;                       // stage s: Asm + s*5120, row pitch 40
    __half* Bsm = (__half*)(smraw + 30720);             // stage s: Bsm + s*4352, row pitch 136
    float* biass = (float*)(smraw + 56832);

    const int KT = 4;
    int tid = threadIdx.x;
    int lane = tid & 31, wid = tid >> 5;
    int warp_m = wid & 3, warp_n = wid >> 2;
    int bn = blockIdx.x * 128, bm = blockIdx.y * 128;

    if (tid < 128) biass[tid] = bias[bn + tid];

    float acc[2][8][4];
#pragma unroll
    for (int i = 0; i < 2; i++)
#pragma unroll
        for (int j = 0; j < 8; j++)
#pragma unroll
            for (int r = 0; r < 4; r++) acc[i][j][r] = 0.0f;

    int arow = tid >> 2, acol = (tid & 3) * 8;          // A: 64 rows/pass, 2 passes
    int brow = tid >> 4, bcol = (tid & 15) * 8;         // B: 16 rows/pass, 2 passes

    auto issue = [&](int kt) {
        int s = kt % 3;
        const __half* agp = g_Af + (size_t)(bm + arow) * 128 + kt * 32 + acol;
#pragma unroll
        for (int h = 0; h < 2; h++) {
            unsigned d = smem_u32(Asm + s * 5120 + (arow + h * 64) * 40 + acol);
            asm volatile("cp.async.cg.shared.global [%0], [%1], 16;\n" :: "r"(d),
                         "l"(agp + (size_t)h * 64 * 128));
        }
        const __half* bgp = g_Bf + (size_t)(kt * 32 + brow) * 4096 + bn + bcol;
#pragma unroll
        for (int h = 0; h < 2; h++) {
            unsigned d = smem_u32(Bsm + s * 4352 + (brow + h * 16) * 136 + bcol);
            asm volatile("cp.async.cg.shared.global [%0], [%1], 16;\n" :: "r"(d),
                         "l"(bgp + (size_t)h * 16 * 4096));
        }
        asm volatile("cp.async.commit_group;\n");
    };

    issue(0);
    issue(1);

#pragma unroll 1
    for (int kt = 0; kt < KT; kt++) {
        int s = kt % 3;
        if (kt < KT - 1) asm volatile("cp.async.wait_group 1;\n" ::: "memory");
        else             asm volatile("cp.async.wait_group 0;\n" ::: "memory");
        __syncthreads();
        if (kt + 2 < KT) issue(kt + 2);

        __half* Ab = Asm + s * 5120;
        __half* Bb = Bsm + s * 4352;
#pragma unroll
        for (int ks = 0; ks < 2; ks++) {
            unsigned a[2][4];
#pragma unroll
            for (int mt = 0; mt < 2; mt++) {
                unsigned addr = smem_u32(Ab + (warp_m * 32 + mt * 16 + (lane & 15)) * 40
                                            + ks * 16 + (lane >> 4) * 8);
                asm volatile("ldmatrix.sync.aligned.m8n8.x4.shared.b16 {%0,%1,%2,%3}, [%4];\n"
                             : "=r"(a[mt][0]), "=r"(a[mt][1]), "=r"(a[mt][2]), "=r"(a[mt][3])
                             : "r"(addr));
            }
            unsigned b[4][4];
#pragma unroll
            for (int p = 0; p < 4; p++) {
                unsigned addr = smem_u32(Bb + (ks * 16 + (lane & 15)) * 136
                                            + warp_n * 64 + p * 16 + (lane >> 4) * 8);
                asm volatile("ldmatrix.sync.aligned.m8n8.x4.trans.shared.b16 {%0,%1,%2,%3}, [%4];\n"
                             : "=r"(b[p][0]), "=r"(b[p][1]), "=r"(b[p][2]), "=r"(b[p][3])
                             : "r"(addr));
            }
#pragma unroll
            for (int mt = 0; mt < 2; mt++)
#pragma unroll
                for (int nt = 0; nt < 8; nt++) {
                    unsigned b0 = b[nt >> 1][(nt & 1) * 2];
                    unsigned b1 = b[nt >> 1][(nt & 1) * 2 + 1];
                    asm volatile(
                        "mma.sync.aligned.m16n8k16.row.col.f32.f16.f16.f32 "
                        "{%0,%1,%2,%3}, {%4,%5,%6,%7}, {%8,%9}, {%0,%1,%2,%3};\n"
                        : "+f"(acc[mt][nt][0]), "+f"(acc[mt][nt][1]),
                          "+f"(acc[mt][nt][2]), "+f"(acc[mt][nt][3])
                        : "r"(a[mt][0]), "r"(a[mt][1]), "r"(a[mt][2]), "r"(a[mt][3]),
                          "r"(b0), "r"(b1));
                }
        }
        __syncthreads();
    }

    // epilogue: bias + fp16 -> smem stage -> coalesced 16B stores
    uint32_t* stage = (uint32_t*)smraw;                 // [128][66]
#pragma unroll
    for (int mt = 0; mt < 2; mt++) {
        int r0 = warp_m * 32 + mt * 16 + (lane >> 2);
#pragma unroll
        for (int nt = 0; nt < 8; nt++) {
            int colL = warp_n * 64 + nt * 8 + (lane & 3) * 2;
            float b0 = biass[colL], b1 = biass[colL + 1];
            __half2 v0 = __floats2half2_rn(acc[mt][nt][0] + b0, acc[mt][nt][1] + b1);
            __half2 v1 = __floats2half2_rn(acc[mt][nt][2] + b0, acc[mt][nt][3] + b1);
            stage[r0 * 66 + (colL >> 1)] = *(uint32_t*)&v0;
            stage[(r0 + 8) * 66 + (colL >> 1)] = *(uint32_t*)&v1;
        }
    }
    __syncthreads();
    {
        int row = tid >> 1, half = tid & 1;
        uint4* dst = (uint4*)(g_We_h + (size_t)(bm + row) * 4096 + bn + half * 64);
        uint32_t* srcp = stage + row * 66 + half * 32;
#pragma unroll
        for (int q = 0; q < 8; q++)
            dst[q] = make_uint4(srcp[q * 4], srcp[q * 4 + 1], srcp[q * 4 + 2], srcp[q * 4 + 3]);
    }
}

// ---------------- message + scatter (fp16 We, half2, vector red) ----------------
__global__ void __launch_bounds__(256) k_msg(const int* __restrict__ src,
                                             const int* __restrict__ dstv) {
    int tid = threadIdx.x, lane = tid & 31, w = tid >> 5;
    int e = blockIdx.x * 8 + w;
    __shared__ float os[8][64];
    int s = src[e];
    os[w][lane] = g_out[s * 64 + lane];
    os[w][32 + lane] = g_out[s * 64 + 32 + lane];
    __syncwarp();
    const __half2* wp = (const __half2*)(g_We_h + (size_t)e * 4096) + lane;
    float accx = 0.0f, accy = 0.0f;
#pragma unroll 8
    for (int i = 0; i < 64; i++) {
        float2 f = __half22float2(__ldg(&wp[i * 32]));
        float o = os[w][i];
        accx += o * f.x; accy += o * f.y;
    }
    int d = dstv[e];
    asm volatile("red.global.add.v2.f32 [%0], {%1,%2};"
                 :: "l"(&g_agg[(size_t)d * 64 + lane * 2]), "f"(accx), "f"(accy) : "memory");
}

// ---------------- node update: conv + relu + GRU, zeroes agg ----------------
__global__ void __launch_bounds__(256) k_node(const float* __restrict__ conv_root,
                                              const float* __restrict__ conv_bias,
                                              const float* __restrict__ wih,
                                              const float* __restrict__ whh,
                                              const float* __restrict__ bihg,
                                              const float* __restrict__ bhhg) {
    extern __shared__ float sm[];
    float* conv = sm;
    float* wihT = conv + 4096;
    float* whhT = wihT + 12288;
    float* cb   = whhT + 12288;
    float* bih  = cb + 64;
    float* bhh  = bih + 192;
    float* outs = bhh + 192;
    float* ms   = outs + 512;

    int tid = threadIdx.x;
    for (int idx = tid; idx < 4096; idx += 256) conv[idx] = conv_root[idx];
    for (int idx = tid; idx < 12288; idx += 256) {
        int j = idx / 64, i = idx % 64;
        wihT[i * 192 + j] = wih[idx];
        whhT[i * 192 + j] = whh[idx];
    }
    if (tid < 64) cb[tid] = conv_bias[tid];
    if (tid < 192) { bih[tid] = bihg[tid]; bhh[tid] = bhhg[tid]; }
    __syncthreads();

    int d = tid & 63, gq = tid >> 6;
    int blockStart = blockIdx.x * 64;

    for (int pass = 0; pass < 8; pass++) {
        __syncthreads();
        int n0 = blockStart + pass * 8 + gq * 2;
        int n1 = n0 + 1;
        outs[(gq * 2 + 0) * 64 + d] = g_out[n0 * 64 + d];
        outs[(gq * 2 + 1) * 64 + d] = g_out[n1 * 64 + d];
        __syncthreads();

        float di0 = 1.0f / fmaxf(g_deg[n0], 1.0f);
        float di1 = 1.0f / fmaxf(g_deg[n1], 1.0f);
        float a0 = g_agg[n0 * 64 + d] * di0 + cb[d];
        float a1 = g_agg[n1 * 64 + d] * di1 + cb[d];
        g_agg[n0 * 64 + d] = 0.0f;
        g_agg[n1 * 64 + d] = 0.0f;

        const float* o0 = &outs[(gq * 2) * 64];
        const float* o1 = o0 + 64;
#pragma unroll 8
        for (int i = 0; i < 64; i++) {
            float c = conv[i * 64 + d];
            a0 += o0[i] * c;
            a1 += o1[i] * c;
        }
        float m0 = fmaxf(a0, 0.0f), m1 = fmaxf(a1, 0.0f);
        ms[(gq * 2) * 64 + d] = m0;
        ms[(gq * 2 + 1) * 64 + d] = m1;
        __syncthreads();

        float gr0 = bih[d], gz0 = bih[64 + d], gn0 = bih[128 + d];
        float gr1 = gr0,    gz1 = gz0,         gn1 = gn0;
        float hr0 = bhh[d], hz0 = bhh[64 + d], hn0 = bhh[128 + d];
        float hr1 = hr0,    hz1 = hz0,         hn1 = hn0;
        const float* mm0 = &ms[(gq * 2) * 64];
        const float* mm1 = mm0 + 64;
#pragma unroll 4
        for (int i = 0; i < 64; i++) {
            float w0 = wihT[i * 192 + d], w1 = wihT[i * 192 + 64 + d], w2 = wihT[i * 192 + 128 + d];
            float u0 = whhT[i * 192 + d], u1 = whhT[i * 192 + 64 + d], u2 = whhT[i * 192 + 128 + d];
            float mi0 = mm0[i], mi1 = mm1[i], oi0 = o0[i], oi1 = o1[i];
            gr0 += mi0 * w0; gz0 += mi0 * w1; gn0 += mi0 * w2;
            gr1 += mi1 * w0; gz1 += mi1 * w1; gn1 += mi1 * w2;
            hr0 += oi0 * u0; hz0 += oi0 * u1; hn0 += oi0 * u2;
            hr1 += oi1 * u0; hz1 += oi1 * u1; hn1 += oi1 * u2;
        }
        {
            float r = sigm(gr0 + hr0);
            float z = sigm(gz0 + hz0);
            float nv = tanhf(gn0 + r * hn0);
            g_out[n0 * 64 + d] = (1.0f - z) * nv + z * o0[d];
        }
        {
            float r = sigm(gr1 + hr1);
            float z = sigm(gz1 + hz1);
            float nv = tanhf(gn1 + r * hn1);
            g_out[n1 * 64 + d] = (1.0f - z) * nv + z * o1[d];
        }
    }
}

// ---------------- Set2Set + head ----------------
__global__ void __launch_bounds__(256) k_s2s(const float* __restrict__ wih,
                                             const float* __restrict__ whh,
                                             const float* __restrict__ bih,
                                             const float* __restrict__ bhh,
                                             const float* __restrict__ l1w,
                                             const float* __restrict__ l1b,
                                             const float* __restrict__ l2w,
                                             const float* __restrict__ l2b,
                                             float* __restrict__ y) {
    int g = blockIdx.x, tid = threadIdx.x;
    __shared__ float qstar[128], hl[64], cl[64], gsm[256], a_sm[256], red[256], rvp[256];
    __shared__ float s_inv;
    if (tid < 128) qstar[tid] = 0.0f;
    if (tid < 64) { hl[tid] = 0.0f; cl[tid] = 0.0f; }
    int start = g_ptr[g], cnt = g_ptr[g + 1] - start;
    __syncthreads();
    int d = tid & 63, gq = tid >> 6;

    for (int step = 0; step < 3; step++) {
        float acc = bih[tid] + bhh[tid];
        const float* wr = wih + tid * 128;
#pragma unroll 8
        for (int i = 0; i < 128; i++) acc += qstar[i] * wr[i];
        const float* ur = whh + tid * 64;
#pragma unroll 8
        for (int i = 0; i < 64; i++) acc += hl[i] * ur[i];
        gsm[tid] = acc;
        __syncthreads();
        if (tid < 64) {
            float ii = sigm(gsm[tid]);
            float ff = sigm(gsm[64 + tid]);
            float gg = tanhf(gsm[128 + tid]);
            float oo = sigm(gsm[192 + tid]);
            float c = ff * cl[tid] + ii * gg;
            cl[tid] = c;
            hl[tid] = oo * tanhf(c);
        }
        __syncthreads();

        float lmax = -3.0e38f;
        for (int j = tid; j < cnt; j += 256) {
            const float* orow = g_out + (size_t)(start + j) * 64;
            float e = 0.0f;
#pragma unroll 8
            for (int k2 = 0; k2 < 64; k2++) e += orow[k2] * hl[k2];
            lmax = fmaxf(lmax, e);
        }
        red[tid] = lmax;
        __syncthreads();
        for (int s = 128; s; s >>= 1) { if (tid < s) red[tid] = fmaxf(red[tid], red[tid + s]); __syncthreads(); }
        float emax = red[0];
        __syncthreads();

        float rv = 0.0f, asum = 0.0f;
        for (int base = 0; base < cnt; base += 256) {
            int chunk = min(256, cnt - base);
            if (tid < chunk) {
                const float* orow = g_out + (size_t)(start + base + tid) * 64;
                float e = 0.0f;
#pragma unroll 8
                for (int k2 = 0; k2 < 64; k2++) e += orow[k2] * hl[k2];
                a_sm[tid] = expf(e - emax);
            }
            __syncthreads();
            for (int j = gq; j < chunk; j += 4) {
                float a = a_sm[j];
                rv += a * g_out[(size_t)(start + base + j) * 64 + d];
                if (d == 0) asum += a;
            }
            __syncthreads();
        }
        rvp[tid] = rv;
        red[tid] = (d == 0) ? asum : 0.0f;
        __syncthreads();
        if (tid == 0) s_inv = 1.0f / (red[0] + red[64] + red[128] + red[192] + 1e-16f);
        __syncthreads();
        if (tid < 64) {
            float rvt = rvp[tid] + rvp[64 + tid] + rvp[128 + tid] + rvp[192 + tid];
            qstar[tid] = hl[tid];
            qstar[64 + tid] = rvt * s_inv;
        }
        __syncthreads();
    }

    float t = 0.0f;
    if (tid < 64) {
        float acc = l1b[tid];
#pragma unroll 8
        for (int i = 0; i < 128; i++) acc += qstar[i] * l1w[i * 64 + tid];
        t = fmaxf(acc, 0.0f) * l2w[tid];
    }
    red[tid] = (tid < 64) ? t : 0.0f;
    __syncthreads();
    for (int s = 128; s; s >>= 1) { if (tid < s) red[tid] += red[tid + s]; __syncthreads(); }
    if (tid == 0) y[g] = red[0] + l2b[0];
}

// ---------------- host launcher ----------------
extern "C" void kernel_launch(void* const* d_in, const int* in_sizes, int n_in,
                              void* d_out, int out_size) {
    const float* x        = (const float*)d_in[0];
    const int*   ei       = (const int*)  d_in[1];
    const float* ea       = (const float*)d_in[2];
    const int*   batch    = (const int*)  d_in[3];
    const float* lin0_w   = (const float*)d_in[4];
    const float* lin0_b   = (const float*)d_in[5];
    const float* nn_w1    = (const float*)d_in[6];
    const float* nn_b1    = (const float*)d_in[7];
    const float* nn_w2    = (const float*)d_in[8];
    const float* nn_b2    = (const float*)d_in[9];
    const float* conv_root= (const float*)d_in[10];
    const float* conv_bias= (const float*)d_in[11];
    const float* gru_wih  = (const float*)d_in[12];
    const float* gru_whh  = (const float*)d_in[13];
    const float* gru_bih  = (const float*)d_in[14];
    const float* gru_bhh  = (const float*)d_in[15];
    const float* lstm_wih = (const float*)d_in[16];
    const float* lstm_whh = (const float*)d_in[17];
    const float* lstm_bih = (const float*)d_in[18];
    const float* lstm_bhh = (const float*)d_in[19];
    const float* lin1_w   = (const float*)d_in[20];
    const float* lin1_b   = (const float*)d_in[21];
    const float* lin2_w   = (const float*)d_in[22];
    const float* lin2_b   = (const float*)d_in[23];
    float* y = (float*)d_out;

    const int* src  = ei;
    const int* dstv = ei + EE;

    const int NODE_SMEM = 30144 * 4;
    cudaFuncSetAttribute(k_node, cudaFuncAttributeMaxDynamicSharedMemorySize, NODE_SMEM);
    const int GEMM_SMEM = 57344;     // 56832 data + 512 bias
    cudaFuncSetAttribute(k_gemm_f16, cudaFuncAttributeMaxDynamicSharedMemorySize, GEMM_SMEM);

    // GEMM chain first (puts k_gemm_f16 at the profiled launch slot)
    k_mlp1<<<EE / 2, 256>>>(ea, nn_w1, nn_b1);
    k_cvtA<<<EE * 128 / 512, 256>>>();
    k_cvtB<<<128 * 4096 / 512, 256>>>(nn_w2);
    k_gemm_f16<<<dim3(32, 256), 256, GEMM_SMEM>>>(nn_b2);

    k_init<<<NN * DIM / 256, 256>>>();
    k_lin0<<<NN / 4, 256>>>(x, lin0_w, lin0_b);
    k_ptr<<<3, 256>>>(batch);
    k_deg<<<EE / 256, 256>>>(dstv);

    for (int it = 0; it < 6; it++) {
        k_msg<<<EE / 8, 256>>>(src, dstv);
        k_node<<<NN / 64, 256, NODE_SMEM>>>(conv_root, conv_bias,
                                            gru_wih, gru_whh, gru_bih, gru_bhh);
    }

    k_s2s<<<NGR, 256>>>(lstm_wih, lstm_whh, lstm_bih, lstm_bhh,
                        lin1_w, lin1_b, lin2_w, lin2_b, y);
}

// round 5
// speedup vs baseline: 1.5555x; 1.0015x over previous
#include <cuda_runtime.h>
#include <cuda_fp16.h>
#include <math.h>
#include <stdint.h>

#define NN   16384
#define EE   32768
#define DIM  64
#define NGR  512

// ---------------- device scratch ----------------
__device__ float g_out[NN * DIM];                 // node state
__device__ float g_H[EE * 128];                   // edge MLP hidden (fp32)
__device__ __half g_Af[EE * 128];                 // A in fp16 [E,128]
__device__ __half g_Bf[128 * 4096];               // B in fp16 [128,4096]
__device__ __half g_We_h[(size_t)EE * 4096];      // per-edge 64x64 weights, fp16 (256MB)
__device__ float g_agg[NN * DIM];
__device__ float g_deg[NN];
__device__ int   g_ptr[NGR + 1];

__device__ __forceinline__ float sigm(float x) { return 1.0f / (1.0f + expf(-x)); }
__device__ __forceinline__ unsigned smem_u32(const void* p) {
    return (unsigned)__cvta_generic_to_shared(p);
}

// ---------------- init ----------------
__global__ void k_init() {
    int i = blockIdx.x * 256 + threadIdx.x;
    if (i < NN) g_deg[i] = 0.0f;
    if (i < NN * DIM) g_agg[i] = 0.0f;
}

// ---------------- lin0 ----------------
__global__ void __launch_bounds__(256) k_lin0(const float* __restrict__ x,
                                              const float* __restrict__ w,
                                              const float* __restrict__ b) {
    __shared__ float ws[29 * 64];
    __shared__ float xs[4][32];
    int tid = threadIdx.x;
    int d = tid & 63, gq = tid >> 6;
    for (int i = tid; i < 29 * 64; i += 256) ws[i] = w[i];
    int n = blockIdx.x * 4 + gq;
    if (d < 29) xs[gq][d] = x[n * 29 + d];
    __syncthreads();
    float acc = b[d];
#pragma unroll
    for (int j = 0; j < 29; j++) acc += xs[gq][j] * ws[j * 64 + d];
    g_out[n * 64 + d] = fmaxf(acc, 0.0f);
}

// ---------------- graph offsets ----------------
__global__ void k_ptr(const int* __restrict__ batch) {
    int g = blockIdx.x * blockDim.x + threadIdx.x;
    if (g > NGR) return;
    if (g == NGR) { g_ptr[g] = NN; return; }
    int lo = 0, hi = NN;
    while (lo < hi) { int mid = (lo + hi) >> 1; if (batch[mid] < g) lo = mid + 1; else hi = mid; }
    g_ptr[g] = lo;
}

// ---------------- degree ----------------
__global__ void k_deg(const int* __restrict__ dstv) {
    int e = blockIdx.x * 256 + threadIdx.x;
    if (e < EE) atomicAdd(&g_deg[dstv[e]], 1.0f);
}

// ---------------- edge MLP layer 1 ----------------
__global__ void __launch_bounds__(256) k_mlp1(const float* __restrict__ ea,
                                              const float* __restrict__ w1,
                                              const float* __restrict__ b1) {
    __shared__ float ws[6 * 128];
    __shared__ float bs[128];
    __shared__ float es[2][8];
    int tid = threadIdx.x;
    int k = tid & 127, gq = tid >> 7;
    for (int i = tid; i < 768; i += 256) ws[i] = w1[i];
    if (tid < 128) bs[tid] = b1[tid];
    int e = blockIdx.x * 2 + gq;
    if (k < 6) es[gq][k] = ea[e * 6 + k];
    __syncthreads();
    float acc = bs[k];
#pragma unroll
    for (int j = 0; j < 6; j++) acc += es[gq][j] * ws[j * 128 + k];
    g_H[e * 128 + k] = fmaxf(acc, 0.0f);
}

// ---------------- convert A: g_H fp32 -> g_Af fp16 ----------------
__global__ void k_cvtA() {
    int i = blockIdx.x * 256 + threadIdx.x;     // over E*128/2
    float2 v = *(const float2*)&g_H[i * 2];
    *(__half2*)&g_Af[i * 2] = __floats2half2_rn(v.x, v.y);
}

// ---------------- convert B: nn_w2 fp32 -> g_Bf fp16 ----------------
__global__ void k_cvtB(const float* __restrict__ w2) {
    int i = blockIdx.x * 256 + threadIdx.x;     // over 128*4096/2
    float2 v = *(const float2*)&w2[i * 2];
    *(__half2*)&g_Bf[i * 2] = __floats2half2_rn(v.x, v.y);
}

// ---------------- fp16 tensor-core GEMM: [32768,128]@[128,4096] + bias -> fp16 ----------------
// 128x128 tile, BK=32, KT=4, 3-stage cp.async, 256 threads (8 warps 4x2).
// Dynamic smem: A stages @ s*10240 (128x40 halfs), B stages @ 30720+s*8704 (32x136 halfs),
// bias @ 56832. Epilogue stage[128][66] u32 aliases bytes [0,33792).
__global__ void __launch_bounds__(256) k_gemm_f16(const float* __restrict__ bias) {
    extern __shared__ __align__(16) char smraw[];
    __half* Asm = (__half*)smraw;                       // stage s: Asm + s*5120, row pitch 40
    __half* Bsm = (__half*)(smraw + 30720);             // stage s: Bsm + s*4352, row pitch 136
    float* biass = (float*)(smraw + 56832);

    const int KT = 4;
    int tid = threadIdx.x;
    int lane = tid & 31, wid = tid >> 5;
    int warp_m = wid & 3, warp_n = wid >> 2;
    int bn = blockIdx.x * 128, bm = blockIdx.y * 128;

    if (tid < 128) biass[tid] = bias[bn + tid];

    float acc[2][8][4];
#pragma unroll
    for (int i = 0; i < 2; i++)
#pragma unroll
        for (int j = 0; j < 8; j++)
#pragma unroll
            for (int r = 0; r < 4; r++) acc[i][j][r] = 0.0f;

    int arow = tid >> 2, acol = (tid & 3) * 8;          // A: 64 rows/pass, 2 passes
    int brow = tid >> 4, bcol = (tid & 15) * 8;         // B: 16 rows/pass, 2 passes

    auto issue = [&](int kt) {
        int s = kt % 3;
        const __half* agp = g_Af + (size_t)(bm + arow) * 128 + kt * 32 + acol;
#pragma unroll
        for (int h = 0; h < 2; h++) {
            unsigned d = smem_u32(Asm + s * 5120 + (arow + h * 64) * 40 + acol);
            asm volatile("cp.async.cg.shared.global [%0], [%1], 16;\n" :: "r"(d),
                         "l"(agp + (size_t)h * 64 * 128));
        }
        const __half* bgp = g_Bf + (size_t)(kt * 32 + brow) * 4096 + bn + bcol;
#pragma unroll
        for (int h = 0; h < 2; h++) {
            unsigned d = smem_u32(Bsm + s * 4352 + (brow + h * 16) * 136 + bcol);
            asm volatile("cp.async.cg.shared.global [%0], [%1], 16;\n" :: "r"(d),
                         "l"(bgp + (size_t)h * 16 * 4096));
        }
        asm volatile("cp.async.commit_group;\n");
    };

    issue(0);
    issue(1);

#pragma unroll 1
    for (int kt = 0; kt < KT; kt++) {
        int s = kt % 3;
        if (kt < KT - 1) asm volatile("cp.async.wait_group 1;\n" ::: "memory");
        else             asm volatile("cp.async.wait_group 0;\n" ::: "memory");
        __syncthreads();
        if (kt + 2 < KT) issue(kt + 2);

        __half* Ab = Asm + s * 5120;
        __half* Bb = Bsm + s * 4352;
#pragma unroll
        for (int ks = 0; ks < 2; ks++) {
            unsigned a[2][4];
#pragma unroll
            for (int mt = 0; mt < 2; mt++) {
                unsigned addr = smem_u32(Ab + (warp_m * 32 + mt * 16 + (lane & 15)) * 40
                                            + ks * 16 + (lane >> 4) * 8);
                asm volatile("ldmatrix.sync.aligned.m8n8.x4.shared.b16 {%0,%1,%2,%3}, [%4];\n"
                             : "=r"(a[mt][0]), "=r"(a[mt][1]), "=r"(a[mt][2]), "=r"(a[mt][3])
                             : "r"(addr));
            }
            unsigned b[4][4];
#pragma unroll
            for (int p = 0; p < 4; p++) {
                unsigned addr = smem_u32(Bb + (ks * 16 + (lane & 15)) * 136
                                            + warp_n * 64 + p * 16 + (lane >> 4) * 8);
                asm volatile("ldmatrix.sync.aligned.m8n8.x4.trans.shared.b16 {%0,%1,%2,%3}, [%4];\n"
                             : "=r"(b[p][0]), "=r"(b[p][1]), "=r"(b[p][2]), "=r"(b[p][3])
                             : "r"(addr));
            }
#pragma unroll
            for (int mt = 0; mt < 2; mt++)
#pragma unroll
                for (int nt = 0; nt < 8; nt++) {
                    unsigned b0 = b[nt >> 1][(nt & 1) * 2];
                    unsigned b1 = b[nt >> 1][(nt & 1) * 2 + 1];
                    asm volatile(
                        "mma.sync.aligned.m16n8k16.row.col.f32.f16.f16.f32 "
                        "{%0,%1,%2,%3}, {%4,%5,%6,%7}, {%8,%9}, {%0,%1,%2,%3};\n"
                        : "+f"(acc[mt][nt][0]), "+f"(acc[mt][nt][1]),
                          "+f"(acc[mt][nt][2]), "+f"(acc[mt][nt][3])
                        : "r"(a[mt][0]), "r"(a[mt][1]), "r"(a[mt][2]), "r"(a[mt][3]),
                          "r"(b0), "r"(b1));
                }
        }
        __syncthreads();
    }

    // epilogue: bias + fp16 -> smem stage -> coalesced 16B stores
    uint32_t* stage = (uint32_t*)smraw;                 // [128][66]
#pragma unroll
    for (int mt = 0; mt < 2; mt++) {
        int r0 = warp_m * 32 + mt * 16 + (lane >> 2);
#pragma unroll
        for (int nt = 0; nt < 8; nt++) {
            int colL = warp_n * 64 + nt * 8 + (lane & 3) * 2;
            float b0 = biass[colL], b1 = biass[colL + 1];
            __half2 v0 = __floats2half2_rn(acc[mt][nt][0] + b0, acc[mt][nt][1] + b1);
            __half2 v1 = __floats2half2_rn(acc[mt][nt][2] + b0, acc[mt][nt][3] + b1);
            stage[r0 * 66 + (colL >> 1)] = *(uint32_t*)&v0;
            stage[(r0 + 8) * 66 + (colL >> 1)] = *(uint32_t*)&v1;
        }
    }
    __syncthreads();
    {
        int row = tid >> 1, half = tid & 1;
        uint4* dst = (uint4*)(g_We_h + (size_t)(bm + row) * 4096 + bn + half * 64);
        uint32_t* srcp = stage + row * 66 + half * 32;
#pragma unroll
        for (int q = 0; q < 8; q++)
            dst[q] = make_uint4(srcp[q * 4], srcp[q * 4 + 1], srcp[q * 4 + 2], srcp[q * 4 + 3]);
    }
}

// ---------------- message + scatter (fp16 We, half2, vector red) ----------------
__global__ void __launch_bounds__(256) k_msg(const int* __restrict__ src,
                                             const int* __restrict__ dstv) {
    int tid = threadIdx.x, lane = tid & 31, w = tid >> 5;
    int e = blockIdx.x * 8 + w;
    __shared__ float os[8][64];
    int s = src[e];
    os[w][lane] = g_out[s * 64 + lane];
    os[w][32 + lane] = g_out[s * 64 + 32 + lane];
    __syncwarp();
    const __half2* wp = (const __half2*)(g_We_h + (size_t)e * 4096) + lane;
    float accx = 0.0f, accy = 0.0f;
#pragma unroll 8
    for (int i = 0; i < 64; i++) {
        float2 f = __half22float2(__ldg(&wp[i * 32]));
        float o = os[w][i];
        accx += o * f.x; accy += o * f.y;
    }
    int d = dstv[e];
    asm volatile("red.global.add.v2.f32 [%0], {%1,%2};"
                 :: "l"(&g_agg[(size_t)d * 64 + lane * 2]), "f"(accx), "f"(accy) : "memory");
}

// ---------------- node update: conv + relu + GRU, zeroes agg ----------------
__global__ void __launch_bounds__(256) k_node(const float* __restrict__ conv_root,
                                              const float* __restrict__ conv_bias,
                                              const float* __restrict__ wih,
                                              const float* __restrict__ whh,
                                              const float* __restrict__ bihg,
                                              const float* __restrict__ bhhg) {
    extern __shared__ float sm[];
    float* conv = sm;
    float* wihT = conv + 4096;
    float* whhT = wihT + 12288;
    float* cb   = whhT + 12288;
    float* bih  = cb + 64;
    float* bhh  = bih + 192;
    float* outs = bhh + 192;
    float* ms   = outs + 512;

    int tid = threadIdx.x;
    for (int idx = tid; idx < 4096; idx += 256) conv[idx] = conv_root[idx];
    for (int idx = tid; idx < 12288; idx += 256) {
        int j = idx / 64, i = idx % 64;
        wihT[i * 192 + j] = wih[idx];
        whhT[i * 192 + j] = whh[idx];
    }
    if (tid < 64) cb[tid] = conv_bias[tid];
    if (tid < 192) { bih[tid] = bihg[tid]; bhh[tid] = bhhg[tid]; }
    __syncthreads();

    int d = tid & 63, gq = tid >> 6;
    int blockStart = blockIdx.x * 64;

    for (int pass = 0; pass < 8; pass++) {
        __syncthreads();
        int n0 = blockStart + pass * 8 + gq * 2;
        int n1 = n0 + 1;
        outs[(gq * 2 + 0) * 64 + d] = g_out[n0 * 64 + d];
        outs[(gq * 2 + 1) * 64 + d] = g_out[n1 * 64 + d];
        __syncthreads();

        float di0 = 1.0f / fmaxf(g_deg[n0], 1.0f);
        float di1 = 1.0f / fmaxf(g_deg[n1], 1.0f);
        float a0 = g_agg[n0 * 64 + d] * di0 + cb[d];
        float a1 = g_agg[n1 * 64 + d] * di1 + cb[d];
        g_agg[n0 * 64 + d] = 0.0f;
        g_agg[n1 * 64 + d] = 0.0f;

        const float* o0 = &outs[(gq * 2) * 64];
        const float* o1 = o0 + 64;
#pragma unroll 8
        for (int i = 0; i < 64; i++) {
            float c = conv[i * 64 + d];
            a0 += o0[i] * c;
            a1 += o1[i] * c;
        }
        float m0 = fmaxf(a0, 0.0f), m1 = fmaxf(a1, 0.0f);
        ms[(gq * 2) * 64 + d] = m0;
        ms[(gq * 2 + 1) * 64 + d] = m1;
        __syncthreads();

        float gr0 = bih[d], gz0 = bih[64 + d], gn0 = bih[128 + d];
        float gr1 = gr0,    gz1 = gz0,         gn1 = gn0;
        float hr0 = bhh[d], hz0 = bhh[64 + d], hn0 = bhh[128 + d];
        float hr1 = hr0,    hz1 = hz0,         hn1 = hn0;
        const float* mm0 = &ms[(gq * 2) * 64];
        const float* mm1 = mm0 + 64;
#pragma unroll 4
        for (int i = 0; i < 64; i++) {
            float w0 = wihT[i * 192 + d], w1 = wihT[i * 192 + 64 + d], w2 = wihT[i * 192 + 128 + d];
            float u0 = whhT[i * 192 + d], u1 = whhT[i * 192 + 64 + d], u2 = whhT[i * 192 + 128 + d];
            float mi0 = mm0[i], mi1 = mm1[i], oi0 = o0[i], oi1 = o1[i];
            gr0 += mi0 * w0; gz0 += mi0 * w1; gn0 += mi0 * w2;
            gr1 += mi1 * w0; gz1 += mi1 * w1; gn1 += mi1 * w2;
            hr0 += oi0 * u0; hz0 += oi0 * u1; hn0 += oi0 * u2;
            hr1 += oi1 * u0; hz1 += oi1 * u1; hn1 += oi1 * u2;
        }
        {
            float r = sigm(gr0 + hr0);
            float z = sigm(gz0 + hz0);
            float nv = tanhf(gn0 + r * hn0);
            g_out[n0 * 64 + d] = (1.0f - z) * nv + z * o0[d];
        }
        {
            float r = sigm(gr1 + hr1);
            float z = sigm(gz1 + hz1);
            float nv = tanhf(gn1 + r * hn1);
            g_out[n1 * 64 + d] = (1.0f - z) * nv + z * o1[d];
        }
    }
}

// ---------------- Set2Set + head ----------------
__global__ void __launch_bounds__(256) k_s2s(const float* __restrict__ wih,
                                             const float* __restrict__ whh,
                                             const float* __restrict__ bih,
                                             const float* __restrict__ bhh,
                                             const float* __restrict__ l1w,
                                             const float* __restrict__ l1b,
                                             const float* __restrict__ l2w,
                                             const float* __restrict__ l2b,
                                             float* __restrict__ y) {
    int g = blockIdx.x, tid = threadIdx.x;
    __shared__ float qstar[128], hl[64], cl[64], gsm[256], a_sm[256], red[256], rvp[256];
    __shared__ float s_inv;
    if (tid < 128) qstar[tid] = 0.0f;
    if (tid < 64) { hl[tid] = 0.0f; cl[tid] = 0.0f; }
    int start = g_ptr[g], cnt = g_ptr[g + 1] - start;
    __syncthreads();
    int d = tid & 63, gq = tid >> 6;

    for (int step = 0; step < 3; step++) {
        float acc = bih[tid] + bhh[tid];
        const float* wr = wih + tid * 128;
#pragma unroll 8
        for (int i = 0; i < 128; i++) acc += qstar[i] * wr[i];
        const float* ur = whh + tid * 64;
#pragma unroll 8
        for (int i = 0; i < 64; i++) acc += hl[i] * ur[i];
        gsm[tid] = acc;
        __syncthreads();
        if (tid < 64) {
            float ii = sigm(gsm[tid]);
            float ff = sigm(gsm[64 + tid]);
            float gg = tanhf(gsm[128 + tid]);
            float oo = sigm(gsm[192 + tid]);
            float c = ff * cl[tid] + ii * gg;
            cl[tid] = c;
            hl[tid] = oo * tanhf(c);
        }
        __syncthreads();

        float lmax = -3.0e38f;
        for (int j = tid; j < cnt; j += 256) {
            const float* orow = g_out + (size_t)(start + j) * 64;
            float e = 0.0f;
#pragma unroll 8
            for (int k2 = 0; k2 < 64; k2++) e += orow[k2] * hl[k2];
            lmax = fmaxf(lmax, e);
        }
        red[tid] = lmax;
        __syncthreads();
        for (int s = 128; s; s >>= 1) { if (tid < s) red[tid] = fmaxf(red[tid], red[tid + s]); __syncthreads(); }
        float emax = red[0];
        __syncthreads();

        float rv = 0.0f, asum = 0.0f;
        for (int base = 0; base < cnt; base += 256) {
            int chunk = min(256, cnt - base);
            if (tid < chunk) {
                const float* orow = g_out + (size_t)(start + base + tid) * 64;
                float e = 0.0f;
#pragma unroll 8
                for (int k2 = 0; k2 < 64; k2++) e += orow[k2] * hl[k2];
                a_sm[tid] = expf(e - emax);
            }
            __syncthreads();
            for (int j = gq; j < chunk; j += 4) {
                float a = a_sm[j];
                rv += a * g_out[(size_t)(start + base + j) * 64 + d];
                if (d == 0) asum += a;
            }
            __syncthreads();
        }
        rvp[tid] = rv;
        red[tid] = (d == 0) ? asum : 0.0f;
        __syncthreads();
        if (tid == 0) s_inv = 1.0f / (red[0] + red[64] + red[128] + red[192] + 1e-16f);
        __syncthreads();
        if (tid < 64) {
            float rvt = rvp[tid] + rvp[64 + tid] + rvp[128 + tid] + rvp[192 + tid];
            qstar[tid] = hl[tid];
            qstar[64 + tid] = rvt * s_inv;
        }
        __syncthreads();
    }

    float t = 0.0f;
    if (tid < 64) {
        float acc = l1b[tid];
#pragma unroll 8
        for (int i = 0; i < 128; i++) acc += qstar[i] * l1w[i * 64 + tid];
        t = fmaxf(acc, 0.0f) * l2w[tid];
    }
    red[tid] = (tid < 64) ? t : 0.0f;
    __syncthreads();
    for (int s = 128; s; s >>= 1) { if (tid < s) red[tid] += red[tid + s]; __syncthreads(); }
    if (tid == 0) y[g] = red[0] + l2b[0];
}

// ---------------- host launcher ----------------
extern "C" void kernel_launch(void* const* d_in, const int* in_sizes, int n_in,
                              void* d_out, int out_size) {
    const float* x        = (const float*)d_in[0];
    const int*   ei       = (const int*)  d_in[1];
    const float* ea       = (const float*)d_in[2];
    const int*   batch    = (const int*)  d_in[3];
    const float* lin0_w   = (const float*)d_in[4];
    const float* lin0_b   = (const float*)d_in[5];
    const float* nn_w1    = (const float*)d_in[6];
    const float* nn_b1    = (const float*)d_in[7];
    const float* nn_w2    = (const float*)d_in[8];
    const float* nn_b2    = (const float*)d_in[9];
    const float* conv_root= (const float*)d_in[10];
    const float* conv_bias= (const float*)d_in[11];
    const float* gru_wih  = (const float*)d_in[12];
    const float* gru_whh  = (const float*)d_in[13];
    const float* gru_bih  = (const float*)d_in[14];
    const float* gru_bhh  = (const float*)d_in[15];
    const float* lstm_wih = (const float*)d_in[16];
    const float* lstm_whh = (const float*)d_in[17];
    const float* lstm_bih = (const float*)d_in[18];
    const float* lstm_bhh = (const float*)d_in[19];
    const float* lin1_w   = (const float*)d_in[20];
    const float* lin1_b   = (const float*)d_in[21];
    const float* lin2_w   = (const float*)d_in[22];
    const float* lin2_b   = (const float*)d_in[23];
    float* y = (float*)d_out;

    const int* src  = ei;
    const int* dstv = ei + EE;

    const int NODE_SMEM = 30144 * 4;
    cudaFuncSetAttribute(k_node, cudaFuncAttributeMaxDynamicSharedMemorySize, NODE_SMEM);
    const int GEMM_SMEM = 57344;     // 56832 data + 512 bias
    cudaFuncSetAttribute(k_gemm_f16, cudaFuncAttributeMaxDynamicSharedMemorySize, GEMM_SMEM);

    // GEMM chain first (puts k_gemm_f16 at the profiled launch slot)
    k_mlp1<<<EE / 2, 256>>>(ea, nn_w1, nn_b1);
    k_cvtA<<<EE * 128 / 512, 256>>>();
    k_cvtB<<<128 * 4096 / 512, 256>>>(nn_w2);
    k_gemm_f16<<<dim3(32, 256), 256, GEMM_SMEM>>>(nn_b2);

    k_init<<<NN * DIM / 256, 256>>>();
    k_lin0<<<NN / 4, 256>>>(x, lin0_w, lin0_b);
    k_ptr<<<3, 256>>>(batch);
    k_deg<<<EE / 256, 256>>>(dstv);

    for (int it = 0; it < 6; it++) {
        k_msg<<<EE / 8, 256>>>(src, dstv);
        k_node<<<NN / 64, 256, NODE_SMEM>>>(conv_root, conv_bias,
                                            gru_wih, gru_whh, gru_bih, gru_bhh);
    }

    k_s2s<<<NGR, 256>>>(lstm_wih, lstm_whh, lstm_bih, lstm_bhh,
                        lin1_w, lin1_b, lin2_w, lin2_b, y);
}

// round 8
// speedup vs baseline: 1.9901x; 1.2794x over previous
#include <cuda_runtime.h>
#include <cuda_fp16.h>
#include <math.h>
#include <stdint.h>

#define NN   16384
#define EE   32768
#define DIM  64
#define NGR  512

// ---------------- device scratch ----------------
__device__ __align__(256) float g_out[NN * DIM];            // node state
__device__ __align__(256) __half g_Af[EE * 128];            // edge MLP hidden, fp16
__device__ __align__(256) __half g_Bf[128 * 4096];          // nn_w2 fp16
__device__ __align__(256) __half g_We_h[(size_t)EE * 4096]; // per-edge 64x64 weights (256MB)
__device__ __align__(256) float g_agg[NN * DIM];
__device__ float g_deg[NN];
__device__ int   g_ptr[NGR + 1];

__device__ __forceinline__ float sigm(float x) { return 1.0f / (1.0f + expf(-x)); }
__device__ __forceinline__ unsigned smem_u32(const void* p) {
    return (unsigned)__cvta_generic_to_shared(p);
}

// ---------------- fused prologue: edge MLP layer1 (fp16 out) + cvtB ----------------
__global__ void __launch_bounds__(256) k_pre(const float* __restrict__ ea,
                                             const float* __restrict__ w1,
                                             const float* __restrict__ b1,
                                             const float* __restrict__ w2) {
    int tid = threadIdx.x;
    if (blockIdx.x < EE / 2) {
        __shared__ float ws[6 * 128];
        __shared__ float bs[128];
        __shared__ float es[2][8];
        int k = tid & 127, gq = tid >> 7;
        for (int i = tid; i < 768; i += 256) ws[i] = w1[i];
        if (tid < 128) bs[tid] = b1[tid];
        int e = blockIdx.x * 2 + gq;
        if (k < 6) es[gq][k] = ea[e * 6 + k];
        __syncthreads();
        float acc = bs[k];
#pragma unroll
        for (int j = 0; j < 6; j++) acc += es[gq][j] * ws[j * 128 + k];
        g_Af[e * 128 + k] = __float2half_rn(fmaxf(acc, 0.0f));
    } else {
        int idx = (blockIdx.x - EE / 2) * 256 + tid;     // over 128*4096/2 float2
        float2 v = *(const float2*)&w2[(size_t)idx * 2];
        *(__half2*)&g_Bf[(size_t)idx * 2] = __floats2half2_rn(v.x, v.y);
    }
}

// ---------------- lin0 (+ zero agg/deg) ----------------
__global__ void __launch_bounds__(256) k_lin0(const float* __restrict__ x,
                                              const float* __restrict__ w,
                                              const float* __restrict__ b) {
    __shared__ float ws[29 * 64];
    __shared__ float xs[4][32];
    int tid = threadIdx.x;
    int d = tid & 63, gq = tid >> 6;
    for (int i = tid; i < 29 * 64; i += 256) ws[i] = w[i];
    int n = blockIdx.x * 4 + gq;
    if (d < 29) xs[gq][d] = x[n * 29 + d];
    __syncthreads();
    float acc = b[d];
#pragma unroll
    for (int j = 0; j < 29; j++) acc += xs[gq][j] * ws[j * 64 + d];
    g_out[n * 64 + d] = fmaxf(acc, 0.0f);
    g_agg[n * 64 + d] = 0.0f;
    if (d == 0) g_deg[n] = 0.0f;
}

// ---------------- graph offsets ----------------
__global__ void k_ptr(const int* __restrict__ batch) {
    int g = blockIdx.x * blockDim.x + threadIdx.x;
    if (g > NGR) return;
    if (g == NGR) { g_ptr[g] = NN; return; }
    int lo = 0, hi = NN;
    while (lo < hi) { int mid = (lo + hi) >> 1; if (batch[mid] < g) lo = mid + 1; else hi = mid; }
    g_ptr[g] = lo;
}

// ---------------- degree ----------------
__global__ void k_deg(const int* __restrict__ dstv) {
    int e = blockIdx.x * 256 + threadIdx.x;
    if (e < EE) atomicAdd(&g_deg[dstv[e]], 1.0f);
}

// ---------------- fp16 tensor-core GEMM: [32768,128]@[128,4096] + bias -> fp16 ----------------
__global__ void __launch_bounds__(256) k_gemm_f16(const float* __restrict__ bias) {
    extern __shared__ __align__(16) char smraw[];
    __half* Asm = (__half*)smraw;                       // stage s: +s*5120, pitch 40
    __half* Bsm = (__half*)(smraw + 30720);             // stage s: +s*4352, pitch 136
    float* biass = (float*)(smraw + 56832);

    const int KT = 4;
    int tid = threadIdx.x;
    int lane = tid & 31, wid = tid >> 5;
    int warp_m = wid & 3, warp_n = wid >> 2;
    int bn = blockIdx.x * 128, bm = blockIdx.y * 128;

    if (tid < 128) biass[tid] = bias[bn + tid];

    float acc[2][8][4];
#pragma unroll
    for (int i = 0; i < 2; i++)
#pragma unroll
        for (int j = 0; j < 8; j++)
#pragma unroll
            for (int r = 0; r < 4; r++) acc[i][j][r] = 0.0f;

    int arow = tid >> 2, acol = (tid & 3) * 8;
    int brow = tid >> 4, bcol = (tid & 15) * 8;

    auto issue = [&](int kt) {
        int s = kt % 3;
        const __half* agp = g_Af + (size_t)(bm + arow) * 128 + kt * 32 + acol;
#pragma unroll
        for (int h = 0; h < 2; h++) {
            unsigned d = smem_u32(Asm + s * 5120 + (arow + h * 64) * 40 + acol);
            asm volatile("cp.async.cg.shared.global [%0], [%1], 16;\n" :: "r"(d),
                         "l"(agp + (size_t)h * 64 * 128));
        }
        const __half* bgp = g_Bf + (size_t)(kt * 32 + brow) * 4096 + bn + bcol;
#pragma unroll
        for (int h = 0; h < 2; h++) {
            unsigned d = smem_u32(Bsm + s * 4352 + (brow + h * 16) * 136 + bcol);
            asm volatile("cp.async.cg.shared.global [%0], [%1], 16;\n" :: "r"(d),
                         "l"(bgp + (size_t)h * 16 * 4096));
        }
        asm volatile("cp.async.commit_group;\n");
    };

    issue(0);
    issue(1);

#pragma unroll 1
    for (int kt = 0; kt < KT; kt++) {
        int s = kt % 3;
        if (kt < KT - 1) asm volatile("cp.async.wait_group 1;\n" ::: "memory");
        else             asm volatile("cp.async.wait_group 0;\n" ::: "memory");
        __syncthreads();
        if (kt + 2 < KT) issue(kt + 2);

        __half* Ab = Asm + s * 5120;
        __half* Bb = Bsm + s * 4352;
#pragma unroll
        for (int ks = 0; ks < 2; ks++) {
            unsigned a[2][4];
#pragma unroll
            for (int mt = 0; mt < 2; mt++) {
                unsigned addr = smem_u32(Ab + (warp_m * 32 + mt * 16 + (lane & 15)) * 40
                                            + ks * 16 + (lane >> 4) * 8);
                asm volatile("ldmatrix.sync.aligned.m8n8.x4.shared.b16 {%0,%1,%2,%3}, [%4];\n"
                             : "=r"(a[mt][0]), "=r"(a[mt][1]), "=r"(a[mt][2]), "=r"(a[mt][3])
                             : "r"(addr));
            }
            unsigned b[4][4];
#pragma unroll
            for (int p = 0; p < 4; p++) {
                unsigned addr = smem_u32(Bb + (ks * 16 + (lane & 15)) * 136
                                            + warp_n * 64 + p * 16 + (lane >> 4) * 8);
                asm volatile("ldmatrix.sync.aligned.m8n8.x4.trans.shared.b16 {%0,%1,%2,%3}, [%4];\n"
                             : "=r"(b[p][0]), "=r"(b[p][1]), "=r"(b[p][2]), "=r"(b[p][3])
                             : "r"(addr));
            }
#pragma unroll
            for (int mt = 0; mt < 2; mt++)
#pragma unroll
                for (int nt = 0; nt < 8; nt++) {
                    unsigned b0 = b[nt >> 1][(nt & 1) * 2];
                    unsigned b1 = b[nt >> 1][(nt & 1) * 2 + 1];
                    asm volatile(
                        "mma.sync.aligned.m16n8k16.row.col.f32.f16.f16.f32 "
                        "{%0,%1,%2,%3}, {%4,%5,%6,%7}, {%8,%9}, {%0,%1,%2,%3};\n"
                        : "+f"(acc[mt][nt][0]), "+f"(acc[mt][nt][1]),
                          "+f"(acc[mt][nt][2]), "+f"(acc[mt][nt][3])
                        : "r"(a[mt][0]), "r"(a[mt][1]), "r"(a[mt][2]), "r"(a[mt][3]),
                          "r"(b0), "r"(b1));
                }
        }
        __syncthreads();
    }

    uint32_t* stage = (uint32_t*)smraw;                 // [128][66]
#pragma unroll
    for (int mt = 0; mt < 2; mt++) {
        int r0 = warp_m * 32 + mt * 16 + (lane >> 2);
#pragma unroll
        for (int nt = 0; nt < 8; nt++) {
            int colL = warp_n * 64 + nt * 8 + (lane & 3) * 2;
            float b0 = biass[colL], b1 = biass[colL + 1];
            __half2 v0 = __floats2half2_rn(acc[mt][nt][0] + b0, acc[mt][nt][1] + b1);
            __half2 v1 = __floats2half2_rn(acc[mt][nt][2] + b0, acc[mt][nt][3] + b1);
            stage[r0 * 66 + (colL >> 1)] = *(uint32_t*)&v0;
            stage[(r0 + 8) * 66 + (colL >> 1)] = *(uint32_t*)&v1;
        }
    }
    __syncthreads();
    {
        int row = tid >> 1, half = tid & 1;
        uint4* dst = (uint4*)(g_We_h + (size_t)(bm + row) * 4096 + bn + half * 64);
        uint32_t* srcp = stage + row * 66 + half * 32;
#pragma unroll
        for (int q = 0; q < 8; q++)
            dst[q] = make_uint4(srcp[q * 4], srcp[q * 4 + 1], srcp[q * 4 + 2], srcp[q * 4 + 3]);
    }
}

// ---------------- message + scatter: LDG.128, shuffle-reduce, v2 red ----------------
// 1 warp = 1 edge. Lane l: rows {l>>3 + 4k}, output octet 8*(l&7).
__global__ void __launch_bounds__(256) k_msg(const int* __restrict__ src,
                                             const int* __restrict__ dstv) {
    int tid = threadIdx.x, lane = tid & 31, w = tid >> 5;
    int e = blockIdx.x * 8 + w;
    __shared__ __align__(16) float os[8][64];
    int s = src[e];
    *(float2*)&os[w][lane * 2] = *(const float2*)&g_out[(size_t)s * 64 + lane * 2];
    int dn = dstv[e];
    __syncwarp();
    const uint4* wp = (const uint4*)(g_We_h + (size_t)e * 4096);   // 512 uint4
    int r0 = lane >> 3, c8 = lane & 7;
    float acc[8];
#pragma unroll
    for (int j = 0; j < 8; j++) acc[j] = 0.0f;
#pragma unroll
    for (int k = 0; k < 16; k++) {
        int row = k * 4 + r0;
        uint4 v = __ldg(&wp[row * 8 + c8]);
        float o = os[w][row];
        float2 f;
        f = __half22float2(*(__half2*)&v.x); acc[0] += o * f.x; acc[1] += o * f.y;
        f = __half22float2(*(__half2*)&v.y); acc[2] += o * f.x; acc[3] += o * f.y;
        f = __half22float2(*(__half2*)&v.z); acc[4] += o * f.x; acc[5] += o * f.y;
        f = __half22float2(*(__half2*)&v.w); acc[6] += o * f.x; acc[7] += o * f.y;
    }
#pragma unroll
    for (int j = 0; j < 8; j++) {
        acc[j] += __shfl_xor_sync(0xffffffffu, acc[j], 8);
        acc[j] += __shfl_xor_sync(0xffffffffu, acc[j], 16);
    }
    if (r0 == 0) {
        float* dst = &g_agg[(size_t)dn * 64 + c8 * 8];
        asm volatile("red.global.add.v2.f32 [%0], {%1,%2};" :: "l"(dst),     "f"(acc[0]), "f"(acc[1]) : "memory");
        asm volatile("red.global.add.v2.f32 [%0], {%1,%2};" :: "l"(dst + 2), "f"(acc[2]), "f"(acc[3]) : "memory");
        asm volatile("red.global.add.v2.f32 [%0], {%1,%2};" :: "l"(dst + 4), "f"(acc[4]), "f"(acc[5]) : "memory");
        asm volatile("red.global.add.v2.f32 [%0], {%1,%2};" :: "l"(dst + 6), "f"(acc[6]), "f"(acc[7]) : "memory");
    }
}

// ---------------- node update: conv + relu + GRU, fp16 weights, 65KB smem ----------------
// smem: C2[64*33] h2, W[64*99] h2, U[64*99] h2, cb[64], bih[192], bhh[192], outs[512], ms[512]
__global__ void __launch_bounds__(256) k_node(const float* __restrict__ conv_root,
                                              const float* __restrict__ conv_bias,
                                              const float* __restrict__ wih,
                                              const float* __restrict__ whh,
                                              const float* __restrict__ bihg,
                                              const float* __restrict__ bhhg) {
    extern __shared__ __align__(16) char smraw[];
    __half2* C2 = (__half2*)smraw;                 // 2112
    __half2* W  = C2 + 2112;                       // 6336
    __half2* U  = W + 6336;                        // 6336
    float* cb   = (float*)(U + 6336);
    float* bihs = cb + 64;
    float* bhhs = bihs + 192;
    float* outs = bhhs + 192;                      // 512
    float* ms   = outs + 512;                      // 512

    int tid = threadIdx.x;
    for (int f = tid; f < 2048; f += 256) {        // C2[d*33+p] = conv[(2p)*64+d], [(2p+1)*64+d]
        int p = f >> 6, d = f & 63;
        C2[d * 33 + p] = __floats2half2_rn(conv_root[(2 * p) * 64 + d],
                                           conv_root[(2 * p + 1) * 64 + d]);
    }
    for (int f = tid; f < 6144; f += 256) {        // W[d*99 + g*32 + p]
        int d = f / 96, r = f % 96;
        int g = r >> 5, p = r & 31;
        int row = g * 64 + d;
        W[d * 99 + r] = __floats2half2_rn(wih[row * 64 + 2 * p], wih[row * 64 + 2 * p + 1]);
        U[d * 99 + r] = __floats2half2_rn(whh[row * 64 + 2 * p], whh[row * 64 + 2 * p + 1]);
    }
    if (tid < 64) cb[tid] = conv_bias[tid];
    if (tid < 192) { bihs[tid] = bihg[tid]; bhhs[tid] = bhhg[tid]; }
    __syncthreads();

    int d = tid & 63, gq = tid >> 6;
    int blockStart = blockIdx.x * 64;
    const __half2* Wd = W + d * 99;
    const __half2* Ud = U + d * 99;
    const __half2* Cd = C2 + d * 33;

    for (int pass = 0; pass < 8; pass++) {
        __syncthreads();
        int n0 = blockStart + pass * 8 + gq * 2;
        int n1 = n0 + 1;
        outs[(gq * 2 + 0) * 64 + d] = g_out[n0 * 64 + d];
        outs[(gq * 2 + 1) * 64 + d] = g_out[n1 * 64 + d];
        __syncthreads();

        float di0 = 1.0f / fmaxf(g_deg[n0], 1.0f);
        float di1 = 1.0f / fmaxf(g_deg[n1], 1.0f);
        float a0 = g_agg[n0 * 64 + d] * di0 + cb[d];
        float a1 = g_agg[n1 * 64 + d] * di1 + cb[d];
        g_agg[n0 * 64 + d] = 0.0f;
        g_agg[n1 * 64 + d] = 0.0f;

        const float2* o0p = (const float2*)&outs[(gq * 2) * 64];
        const float2* o1p = o0p + 32;
#pragma unroll 8
        for (int p = 0; p < 32; p++) {
            float2 c = __half22float2(Cd[p]);
            float2 ov0 = o0p[p], ov1 = o1p[p];
            a0 += ov0.x * c.x + ov0.y * c.y;
            a1 += ov1.x * c.x + ov1.y * c.y;
        }
        float m0 = fmaxf(a0, 0.0f), m1 = fmaxf(a1, 0.0f);
        ms[(gq * 2) * 64 + d] = m0;
        ms[(gq * 2 + 1) * 64 + d] = m1;
        __syncthreads();

        float gr0 = bihs[d], gz0 = bihs[64 + d], gn0 = bihs[128 + d];
        float gr1 = gr0,    gz1 = gz0,          gn1 = gn0;
        float hr0 = bhhs[d], hz0 = bhhs[64 + d], hn0 = bhhs[128 + d];
        float hr1 = hr0,    hz1 = hz0,          hn1 = hn0;
        const float2* m0p = (const float2*)&ms[(gq * 2) * 64];
        const float2* m1p = m0p + 32;
#pragma unroll 4
        for (int p = 0; p < 32; p++) {
            float2 wr = __half22float2(Wd[p]);
            float2 wz = __half22float2(Wd[32 + p]);
            float2 wn = __half22float2(Wd[64 + p]);
            float2 ur = __half22float2(Ud[p]);
            float2 uz = __half22float2(Ud[32 + p]);
            float2 un = __half22float2(Ud[64 + p]);
            float2 mv0 = m0p[p], mv1 = m1p[p];
            float2 ov0 = o0p[p], ov1 = o1p[p];
            gr0 += mv0.x * wr.x + mv0.y * wr.y;
            gz0 += mv0.x * wz.x + mv0.y * wz.y;
            gn0 += mv0.x * wn.x + mv0.y * wn.y;
            gr1 += mv1.x * wr.x + mv1.y * wr.y;
            gz1 += mv1.x * wz.x + mv1.y * wz.y;
            gn1 += mv1.x * wn.x + mv1.y * wn.y;
            hr0 += ov0.x * ur.x + ov0.y * ur.y;
            hz0 += ov0.x * uz.x + ov0.y * uz.y;
            hn0 += ov0.x * un.x + ov0.y * un.y;
            hr1 += ov1.x * ur.x + ov1.y * ur.y;
            hz1 += ov1.x * uz.x + ov1.y * uz.y;
            hn1 += ov1.x * un.x + ov1.y * un.y;
        }
        {
            float r = sigm(gr0 + hr0);
            float z = sigm(gz0 + hz0);
            float nv = tanhf(gn0 + r * hn0);
            g_out[n0 * 64 + d] = (1.0f - z) * nv + z * outs[(gq * 2) * 64 + d];
        }
        {
            float r = sigm(gr1 + hr1);
            float z = sigm(gz1 + hz1);
            float nv = tanhf(gn1 + r * hn1);
            g_out[n1 * 64 + d] = (1.0f - z) * nv + z * outs[(gq * 2 + 1) * 64 + d];
        }
    }
}

// ---------------- Set2Set + head ----------------
__global__ void __launch_bounds__(256) k_s2s(const float* __restrict__ wih,
                                             const float* __restrict__ whh,
                                             const float* __restrict__ bih,
                                             const float* __restrict__ bhh,
                                             const float* __restrict__ l1w,
                                             const float* __restrict__ l1b,
                                             const float* __restrict__ l2w,
                                             const float* __restrict__ l2b,
                                             float* __restrict__ y) {
    int g = blockIdx.x, tid = threadIdx.x;
    __shared__ float qstar[128], hl[64], cl[64], gsm[256], a_sm[256], red[256], rvp[256];
    __shared__ float s_inv;
    if (tid < 128) qstar[tid] = 0.0f;
    if (tid < 64) { hl[tid] = 0.0f; cl[tid] = 0.0f; }
    int start = g_ptr[g], cnt = g_ptr[g + 1] - start;
    __syncthreads();
    int d = tid & 63, gq = tid >> 6;

    for (int step = 0; step < 3; step++) {
        float acc = bih[tid] + bhh[tid];
        const float* wr = wih + tid * 128;
#pragma unroll 8
        for (int i = 0; i < 128; i++) acc += qstar[i] * wr[i];
        const float* ur = whh + tid * 64;
#pragma unroll 8
        for (int i = 0; i < 64; i++) acc += hl[i] * ur[i];
        gsm[tid] = acc;
        __syncthreads();
        if (tid < 64) {
            float ii = sigm(gsm[tid]);
            float ff = sigm(gsm[64 + tid]);
            float gg = tanhf(gsm[128 + tid]);
            float oo = sigm(gsm[192 + tid]);
            float c = ff * cl[tid] + ii * gg;
            cl[tid] = c;
            hl[tid] = oo * tanhf(c);
        }
        __syncthreads();

        float lmax = -3.0e38f;
        for (int j = tid; j < cnt; j += 256) {
            const float* orow = g_out + (size_t)(start + j) * 64;
            float e = 0.0f;
#pragma unroll 8
            for (int k2 = 0; k2 < 64; k2++) e += orow[k2] * hl[k2];
            lmax = fmaxf(lmax, e);
        }
        red[tid] = lmax;
        __syncthreads();
        for (int s = 128; s; s >>= 1) { if (tid < s) red[tid] = fmaxf(red[tid], red[tid + s]); __syncthreads(); }
        float emax = red[0];
        __syncthreads();

        float rv = 0.0f, asum = 0.0f;
        for (int base = 0; base < cnt; base += 256) {
            int chunk = min(256, cnt - base);
            if (tid < chunk) {
                const float* orow = g_out + (size_t)(start + base + tid) * 64;
                float e = 0.0f;
#pragma unroll 8
                for (int k2 = 0; k2 < 64; k2++) e += orow[k2] * hl[k2];
                a_sm[tid] = expf(e - emax);
            }
            __syncthreads();
            for (int j = gq; j < chunk; j += 4) {
                float a = a_sm[j];
                rv += a * g_out[(size_t)(start + base + j) * 64 + d];
                if (d == 0) asum += a;
            }
            __syncthreads();
        }
        rvp[tid] = rv;
        red[tid] = (d == 0) ? asum : 0.0f;
        __syncthreads();
        if (tid == 0) s_inv = 1.0f / (red[0] + red[64] + red[128] + red[192] + 1e-16f);
        __syncthreads();
        if (tid < 64) {
            float rvt = rvp[tid] + rvp[64 + tid] + rvp[128 + tid] + rvp[192 + tid];
            qstar[tid] = hl[tid];
            qstar[64 + tid] = rvt * s_inv;
        }
        __syncthreads();
    }

    float t = 0.0f;
    if (tid < 64) {
        float acc = l1b[tid];
#pragma unroll 8
        for (int i = 0; i < 128; i++) acc += qstar[i] * l1w[i * 64 + tid];
        t = fmaxf(acc, 0.0f) * l2w[tid];
    }
    red[tid] = (tid < 64) ? t : 0.0f;
    __syncthreads();
    for (int s = 128; s; s >>= 1) { if (tid < s) red[tid] += red[tid + s]; __syncthreads(); }
    if (tid == 0) y[g] = red[0] + l2b[0];
}

// ---------------- host launcher ----------------
extern "C" void kernel_launch(void* const* d_in, const int* in_sizes, int n_in,
                              void* d_out, int out_size) {
    const float* x        = (const float*)d_in[0];
    const int*   ei       = (const int*)  d_in[1];
    const float* ea       = (const float*)d_in[2];
    const int*   batch    = (const int*)  d_in[3];
    const float* lin0_w   = (const float*)d_in[4];
    const float* lin0_b   = (const float*)d_in[5];
    const float* nn_w1    = (const float*)d_in[6];
    const float* nn_b1    = (const float*)d_in[7];
    const float* nn_w2    = (const float*)d_in[8];
    const float* nn_b2    = (const float*)d_in[9];
    const float* conv_root= (const float*)d_in[10];
    const float* conv_bias= (const float*)d_in[11];
    const float* gru_wih  = (const float*)d_in[12];
    const float* gru_whh  = (const float*)d_in[13];
    const float* gru_bih  = (const float*)d_in[14];
    const float* gru_bhh  = (const float*)d_in[15];
    const float* lstm_wih = (const float*)d_in[16];
    const float* lstm_whh = (const float*)d_in[17];
    const float* lstm_bih = (const float*)d_in[18];
    const float* lstm_bhh = (const float*)d_in[19];
    const float* lin1_w   = (const float*)d_in[20];
    const float* lin1_b   = (const float*)d_in[21];
    const float* lin2_w   = (const float*)d_in[22];
    const float* lin2_b   = (const float*)d_in[23];
    float* y = (float*)d_out;

    const int* src  = ei;
    const int* dstv = ei + EE;

    const int NODE_SMEM = 65024;
    cudaFuncSetAttribute(k_node, cudaFuncAttributeMaxDynamicSharedMemorySize, NODE_SMEM);
    const int GEMM_SMEM = 57344;
    cudaFuncSetAttribute(k_gemm_f16, cudaFuncAttributeMaxDynamicSharedMemorySize, GEMM_SMEM);

    // slot 1..3: prologue; slot 4 = k_msg (profiled)
    k_pre<<<EE / 2 + 1024, 256>>>(ea, nn_w1, nn_b1, nn_w2);
    k_gemm_f16<<<dim3(32, 256), 256, GEMM_SMEM>>>(nn_b2);
    k_lin0<<<NN / 4, 256>>>(x, lin0_w, lin0_b);

    k_msg<<<EE / 8, 256>>>(src, dstv);                 // iteration 0 message
    k_deg<<<EE / 256, 256>>>(dstv);
    k_ptr<<<3, 256>>>(batch);
    k_node<<<NN / 64, 256, NODE_SMEM>>>(conv_root, conv_bias,
                                        gru_wih, gru_whh, gru_bih, gru_bhh);

    for (int it = 1; it < 6; it++) {
        k_msg<<<EE / 8, 256>>>(src, dstv);
        k_node<<<NN / 64, 256, NODE_SMEM>>>(conv_root, conv_bias,
                                            gru_wih, gru_whh, gru_bih, gru_bhh);
    }

    k_s2s<<<NGR, 256>>>(lstm_wih, lstm_whh, lstm_bih, lstm_bhh,
                        lin1_w, lin1_b, lin2_w, lin2_b, y);
}

// round 9
// speedup vs baseline: 2.5126x; 1.2625x over previous
#include <cuda_runtime.h>
#include <cuda_fp16.h>
#include <math.h>
#include <stdint.h>

#define NN   16384
#define EE   32768
#define DIM  64
#define NGR  512

// ---------------- device scratch ----------------
__device__ __align__(256) float g_out[NN * DIM];            // node state fp32
__device__ __align__(256) __half g_outh[NN * DIM];          // node state fp16 mirror
__device__ __align__(256) __half g_Af[EE * 128];            // edge MLP hidden, fp16
__device__ __align__(256) __half g_Bf[128 * 4096];          // nn_w2 fp16
__device__ __align__(256) __half g_We_h[(size_t)EE * 4096]; // per-edge weights (256MB)
__device__ __align__(256) float g_agg[NN * DIM];
__device__ __align__(256) __half g_Mh[NN * DIM];            // m (NNConv output) fp16
__device__ __align__(256) float g_gh[NN * 192];             // h @ whh^T + bhh
__device__ __align__(256) float g_gi[NN * 192];             // m @ wih^T + bih
__device__ __align__(256) __half g_Wcat[64 * 256];          // [conv_root | whh^T] fp16
__device__ __align__(256) __half g_WihP[64 * 256];          // wih^T padded fp16
__device__ float g_biasA[256];                              // conv_bias ++ bhh
__device__ float g_biasB[256];                              // bih ++ 0
__device__ float g_deg[NN];
__device__ int   g_ptr[NGR + 1];

__device__ __forceinline__ float sigm(float x) { return 1.0f / (1.0f + expf(-x)); }
__device__ __forceinline__ unsigned smem_u32(const void* p) {
    return (unsigned)__cvta_generic_to_shared(p);
}

// ---------------- fused prologue: edge MLP layer1 (fp16 out) + cvtB ----------------
__global__ void __launch_bounds__(256) k_pre(const float* __restrict__ ea,
                                             const float* __restrict__ w1,
                                             const float* __restrict__ b1,
                                             const float* __restrict__ w2) {
    int tid = threadIdx.x;
    if (blockIdx.x < EE / 2) {
        __shared__ float ws[6 * 128];
        __shared__ float bs[128];
        __shared__ float es[2][8];
        int k = tid & 127, gq = tid >> 7;
        for (int i = tid; i < 768; i += 256) ws[i] = w1[i];
        if (tid < 128) bs[tid] = b1[tid];
        int e = blockIdx.x * 2 + gq;
        if (k < 6) es[gq][k] = ea[e * 6 + k];
        __syncthreads();
        float acc = bs[k];
#pragma unroll
        for (int j = 0; j < 6; j++) acc += es[gq][j] * ws[j * 128 + k];
        g_Af[e * 128 + k] = __float2half_rn(fmaxf(acc, 0.0f));
    } else {
        int idx = (blockIdx.x - EE / 2) * 256 + tid;
        float2 v = *(const float2*)&w2[(size_t)idx * 2];
        *(__half2*)&g_Bf[(size_t)idx * 2] = __floats2half2_rn(v.x, v.y);
    }
}

// ---------------- pack node-update weights ----------------
__global__ void __launch_bounds__(256) k_pack(const float* __restrict__ conv_root,
                                              const float* __restrict__ whh,
                                              const float* __restrict__ wih,
                                              const float* __restrict__ conv_bias,
                                              const float* __restrict__ bhh,
                                              const float* __restrict__ bih) {
    int idx = blockIdx.x * 256 + threadIdx.x;      // 0..16383
    int i = idx >> 8, c = idx & 255;
    g_Wcat[idx] = __float2half_rn(c < 64 ? conv_root[i * 64 + c] : whh[(c - 64) * 64 + i]);
    g_WihP[idx] = __float2half_rn(c < 192 ? wih[c * 64 + i] : 0.0f);
    if (idx < 256) g_biasA[idx] = idx < 64 ? conv_bias[idx] : bhh[idx - 64];
    else if (idx < 512) { int j = idx - 256; g_biasB[j] = j < 192 ? bih[j] : 0.0f; }
}

// ---------------- lin0 (+ zero agg/deg, fp16 mirror) ----------------
__global__ void __launch_bounds__(256) k_lin0(const float* __restrict__ x,
                                              const float* __restrict__ w,
                                              const float* __restrict__ b) {
    __shared__ float ws[29 * 64];
    __shared__ float xs[4][32];
    int tid = threadIdx.x;
    int d = tid & 63, gq = tid >> 6;
    for (int i = tid; i < 29 * 64; i += 256) ws[i] = w[i];
    int n = blockIdx.x * 4 + gq;
    if (d < 29) xs[gq][d] = x[n * 29 + d];
    __syncthreads();
    float acc = b[d];
#pragma unroll
    for (int j = 0; j < 29; j++) acc += xs[gq][j] * ws[j * 64 + d];
    float r = fmaxf(acc, 0.0f);
    g_out[n * 64 + d] = r;
    g_outh[n * 64 + d] = __float2half_rn(r);
    g_agg[n * 64 + d] = 0.0f;
    if (d == 0) g_deg[n] = 0.0f;
}

// ---------------- graph offsets ----------------
__global__ void k_ptr(const int* __restrict__ batch) {
    int g = blockIdx.x * blockDim.x + threadIdx.x;
    if (g > NGR) return;
    if (g == NGR) { g_ptr[g] = NN; return; }
    int lo = 0, hi = NN;
    while (lo < hi) { int mid = (lo + hi) >> 1; if (batch[mid] < g) lo = mid + 1; else hi = mid; }
    g_ptr[g] = lo;
}

// ---------------- degree ----------------
__global__ void k_deg(const int* __restrict__ dstv) {
    int e = blockIdx.x * 256 + threadIdx.x;
    if (e < EE) atomicAdd(&g_deg[dstv[e]], 1.0f);
}

// ---------------- fp16 tensor-core GEMM: We = A[32768,128]@B[128,4096] + bias ----------------
__global__ void __launch_bounds__(256) k_gemm_f16(const float* __restrict__ bias) {
    extern __shared__ __align__(16) char smraw[];
    __half* Asm = (__half*)smraw;                       // stage s: +s*5120, pitch 40
    __half* Bsm = (__half*)(smraw + 30720);             // stage s: +s*4352, pitch 136
    float* biass = (float*)(smraw + 56832);

    const int KT = 4;
    int tid = threadIdx.x;
    int lane = tid & 31, wid = tid >> 5;
    int warp_m = wid & 3, warp_n = wid >> 2;
    int bn = blockIdx.x * 128, bm = blockIdx.y * 128;

    if (tid < 128) biass[tid] = bias[bn + tid];

    float acc[2][8][4];
#pragma unroll
    for (int i = 0; i < 2; i++)
#pragma unroll
        for (int j = 0; j < 8; j++)
#pragma unroll
            for (int r = 0; r < 4; r++) acc[i][j][r] = 0.0f;

    int arow = tid >> 2, acol = (tid & 3) * 8;
    int brow = tid >> 4, bcol = (tid & 15) * 8;

    auto issue = [&](int kt) {
        int s = kt % 3;
        const __half* agp = g_Af + (size_t)(bm + arow) * 128 + kt * 32 + acol;
#pragma unroll
        for (int h = 0; h < 2; h++) {
            unsigned d = smem_u32(Asm + s * 5120 + (arow + h * 64) * 40 + acol);
            asm volatile("cp.async.cg.shared.global [%0], [%1], 16;\n" :: "r"(d),
                         "l"(agp + (size_t)h * 64 * 128));
        }
        const __half* bgp = g_Bf + (size_t)(kt * 32 + brow) * 4096 + bn + bcol;
#pragma unroll
        for (int h = 0; h < 2; h++) {
            unsigned d = smem_u32(Bsm + s * 4352 + (brow + h * 16) * 136 + bcol);
            asm volatile("cp.async.cg.shared.global [%0], [%1], 16;\n" :: "r"(d),
                         "l"(bgp + (size_t)h * 16 * 4096));
        }
        asm volatile("cp.async.commit_group;\n");
    };

    issue(0);
    issue(1);

#pragma unroll 1
    for (int kt = 0; kt < KT; kt++) {
        int s = kt % 3;
        if (kt < KT - 1) asm volatile("cp.async.wait_group 1;\n" ::: "memory");
        else             asm volatile("cp.async.wait_group 0;\n" ::: "memory");
        __syncthreads();
        if (kt + 2 < KT) issue(kt + 2);

        __half* Ab = Asm + s * 5120;
        __half* Bb = Bsm + s * 4352;
#pragma unroll
        for (int ks = 0; ks < 2; ks++) {
            unsigned a[2][4];
#pragma unroll
            for (int mt = 0; mt < 2; mt++) {
                unsigned addr = smem_u32(Ab + (warp_m * 32 + mt * 16 + (lane & 15)) * 40
                                            + ks * 16 + (lane >> 4) * 8);
                asm volatile("ldmatrix.sync.aligned.m8n8.x4.shared.b16 {%0,%1,%2,%3}, [%4];\n"
                             : "=r"(a[mt][0]), "=r"(a[mt][1]), "=r"(a[mt][2]), "=r"(a[mt][3])
                             : "r"(addr));
            }
            unsigned b[4][4];
#pragma unroll
            for (int p = 0; p < 4; p++) {
                unsigned addr = smem_u32(Bb + (ks * 16 + (lane & 15)) * 136
                                            + warp_n * 64 + p * 16 + (lane >> 4) * 8);
                asm volatile("ldmatrix.sync.aligned.m8n8.x4.trans.shared.b16 {%0,%1,%2,%3}, [%4];\n"
                             : "=r"(b[p][0]), "=r"(b[p][1]), "=r"(b[p][2]), "=r"(b[p][3])
                             : "r"(addr));
            }
#pragma unroll
            for (int mt = 0; mt < 2; mt++)
#pragma unroll
                for (int nt = 0; nt < 8; nt++) {
                    unsigned b0 = b[nt >> 1][(nt & 1) * 2];
                    unsigned b1 = b[nt >> 1][(nt & 1) * 2 + 1];
                    asm volatile(
                        "mma.sync.aligned.m16n8k16.row.col.f32.f16.f16.f32 "
                        "{%0,%1,%2,%3}, {%4,%5,%6,%7}, {%8,%9}, {%0,%1,%2,%3};\n"
                        : "+f"(acc[mt][nt][0]), "+f"(acc[mt][nt][1]),
                          "+f"(acc[mt][nt][2]), "+f"(acc[mt][nt][3])
                        : "r"(a[mt][0]), "r"(a[mt][1]), "r"(a[mt][2]), "r"(a[mt][3]),
                          "r"(b0), "r"(b1));
                }
        }
        __syncthreads();
    }

    uint32_t* stage = (uint32_t*)smraw;                 // [128][66]
#pragma unroll
    for (int mt = 0; mt < 2; mt++) {
        int r0 = warp_m * 32 + mt * 16 + (lane >> 2);
#pragma unroll
        for (int nt = 0; nt < 8; nt++) {
            int colL = warp_n * 64 + nt * 8 + (lane & 3) * 2;
            float b0 = biass[colL], b1 = biass[colL + 1];
            __half2 v0 = __floats2half2_rn(acc[mt][nt][0] + b0, acc[mt][nt][1] + b1);
            __half2 v1 = __floats2half2_rn(acc[mt][nt][2] + b0, acc[mt][nt][3] + b1);
            stage[r0 * 66 + (colL >> 1)] = *(uint32_t*)&v0;
            stage[(r0 + 8) * 66 + (colL >> 1)] = *(uint32_t*)&v1;
        }
    }
    __syncthreads();
    {
        int row = tid >> 1, half = tid & 1;
        uint4* dst = (uint4*)(g_We_h + (size_t)(bm + row) * 4096 + bn + half * 64);
        uint32_t* srcp = stage + row * 66 + half * 32;
#pragma unroll
        for (int q = 0; q < 8; q++)
            dst[q] = make_uint4(srcp[q * 4], srcp[q * 4 + 1], srcp[q * 4 + 2], srcp[q * 4 + 3]);
    }
}

// ---------------- message + scatter: LDG.128, shuffle-reduce, v2 red ----------------
__global__ void __launch_bounds__(256) k_msg(const int* __restrict__ src,
                                             const int* __restrict__ dstv) {
    int tid = threadIdx.x, lane = tid & 31, w = tid >> 5;
    int e = blockIdx.x * 8 + w;
    __shared__ __align__(16) float os[8][64];
    int s = src[e];
    *(float2*)&os[w][lane * 2] = *(const float2*)&g_out[(size_t)s * 64 + lane * 2];
    int dn = dstv[e];
    __syncwarp();
    const uint4* wp = (const uint4*)(g_We_h + (size_t)e * 4096);
    int r0 = lane >> 3, c8 = lane & 7;
    float acc[8];
#pragma unroll
    for (int j = 0; j < 8; j++) acc[j] = 0.0f;
#pragma unroll
    for (int k = 0; k < 16; k++) {
        int row = k * 4 + r0;
        uint4 v = __ldg(&wp[row * 8 + c8]);
        float o = os[w][row];
        float2 f;
        f = __half22float2(*(__half2*)&v.x); acc[0] += o * f.x; acc[1] += o * f.y;
        f = __half22float2(*(__half2*)&v.y); acc[2] += o * f.x; acc[3] += o * f.y;
        f = __half22float2(*(__half2*)&v.z); acc[4] += o * f.x; acc[5] += o * f.y;
        f = __half22float2(*(__half2*)&v.w); acc[6] += o * f.x; acc[7] += o * f.y;
    }
#pragma unroll
    for (int j = 0; j < 8; j++) {
        acc[j] += __shfl_xor_sync(0xffffffffu, acc[j], 8);
        acc[j] += __shfl_xor_sync(0xffffffffu, acc[j], 16);
    }
    if (r0 == 0) {
        float* dst = &g_agg[(size_t)dn * 64 + c8 * 8];
        asm volatile("red.global.add.v2.f32 [%0], {%1,%2};" :: "l"(dst),     "f"(acc[0]), "f"(acc[1]) : "memory");
        asm volatile("red.global.add.v2.f32 [%0], {%1,%2};" :: "l"(dst + 2), "f"(acc[2]), "f"(acc[3]) : "memory");
        asm volatile("red.global.add.v2.f32 [%0], {%1,%2};" :: "l"(dst + 4), "f"(acc[4]), "f"(acc[5]) : "memory");
        asm volatile("red.global.add.v2.f32 [%0], {%1,%2};" :: "l"(dst + 6), "f"(acc[6]), "f"(acc[7]) : "memory");
    }
}

// ---------------- gemmA: h_fp16 @ [conv_root | whh^T] (K=64, N=256) ----------------
// epilogue: cols<64 -> m = relu(c + agg*dinv + cb) -> g_Mh, zero agg; cols>=64 -> g_gh
__global__ void __launch_bounds__(256) k_gemmA() {
    __shared__ __half As[128][72];
    __shared__ __half Bs[64][136];
    __shared__ float biass[128];
    int tid = threadIdx.x, lane = tid & 31, wid = tid >> 5;
    int warp_m = wid & 3, warp_n = wid >> 2;
    int bn = blockIdx.x * 128, bm = blockIdx.y * 128;

    if (tid < 128) biass[tid] = g_biasA[bn + tid];

    {
        int ar = tid >> 3, ac = (tid & 7) * 8;
#pragma unroll
        for (int p = 0; p < 4; p++) {
            unsigned d = smem_u32(&As[ar + p * 32][ac]);
            asm volatile("cp.async.cg.shared.global [%0], [%1], 16;\n" :: "r"(d),
                         "l"(g_outh + (size_t)(bm + ar + p * 32) * 64 + ac));
        }
        int br = tid >> 4, bc = (tid & 15) * 8;
#pragma unroll
        for (int p = 0; p < 4; p++) {
            unsigned d = smem_u32(&Bs[br + p * 16][bc]);
            asm volatile("cp.async.cg.shared.global [%0], [%1], 16;\n" :: "r"(d),
                         "l"(g_Wcat + (size_t)(br + p * 16) * 256 + bn + bc));
        }
        asm volatile("cp.async.commit_group;\ncp.async.wait_group 0;\n" ::: "memory");
    }
    __syncthreads();

    float acc[2][8][4];
#pragma unroll
    for (int i = 0; i < 2; i++)
#pragma unroll
        for (int j = 0; j < 8; j++)
#pragma unroll
            for (int r = 0; r < 4; r++) acc[i][j][r] = 0.0f;

#pragma unroll
    for (int ks = 0; ks < 4; ks++) {
        unsigned a[2][4];
#pragma unroll
        for (int mt = 0; mt < 2; mt++) {
            unsigned addr = smem_u32(&As[warp_m * 32 + mt * 16 + (lane & 15)]
                                        [ks * 16 + (lane >> 4) * 8]);
            asm volatile("ldmatrix.sync.aligned.m8n8.x4.shared.b16 {%0,%1,%2,%3}, [%4];\n"
                         : "=r"(a[mt][0]), "=r"(a[mt][1]), "=r"(a[mt][2]), "=r"(a[mt][3])
                         : "r"(addr));
        }
        unsigned b[4][4];
#pragma unroll
        for (int p = 0; p < 4; p++) {
            unsigned addr = smem_u32(&Bs[ks * 16 + (lane & 15)]
                                        [warp_n * 64 + p * 16 + (lane >> 4) * 8]);
            asm volatile("ldmatrix.sync.aligned.m8n8.x4.trans.shared.b16 {%0,%1,%2,%3}, [%4];\n"
                         : "=r"(b[p][0]), "=r"(b[p][1]), "=r"(b[p][2]), "=r"(b[p][3])
                         : "r"(addr));
        }
#pragma unroll
        for (int mt = 0; mt < 2; mt++)
#pragma unroll
            for (int nt = 0; nt < 8; nt++) {
                unsigned b0 = b[nt >> 1][(nt & 1) * 2];
                unsigned b1 = b[nt >> 1][(nt & 1) * 2 + 1];
                asm volatile(
                    "mma.sync.aligned.m16n8k16.row.col.f32.f16.f16.f32 "
                    "{%0,%1,%2,%3}, {%4,%5,%6,%7}, {%8,%9}, {%0,%1,%2,%3};\n"
                    : "+f"(acc[mt][nt][0]), "+f"(acc[mt][nt][1]),
                      "+f"(acc[mt][nt][2]), "+f"(acc[mt][nt][3])
                    : "r"(a[mt][0]), "r"(a[mt][1]), "r"(a[mt][2]), "r"(a[mt][3]),
                      "r"(b0), "r"(b1));
            }
    }

    bool mpath = (bn == 0) && (warp_n == 0);
#pragma unroll
    for (int mt = 0; mt < 2; mt++) {
        int row0 = bm + warp_m * 32 + mt * 16 + (lane >> 2);
        int row1 = row0 + 8;
        float di0 = 0.0f, di1 = 0.0f;
        if (mpath) {
            di0 = 1.0f / fmaxf(g_deg[row0], 1.0f);
            di1 = 1.0f / fmaxf(g_deg[row1], 1.0f);
        }
#pragma unroll
        for (int nt = 0; nt < 8; nt++) {
            int colL = warp_n * 64 + nt * 8 + (lane & 3) * 2;
            int gc = bn + colL;
            float b0 = biass[colL], b1 = biass[colL + 1];
            float v00 = acc[mt][nt][0] + b0, v01 = acc[mt][nt][1] + b1;
            float v10 = acc[mt][nt][2] + b0, v11 = acc[mt][nt][3] + b1;
            if (mpath) {
                float2 a0 = *(float2*)&g_agg[(size_t)row0 * 64 + gc];
                float2 a1 = *(float2*)&g_agg[(size_t)row1 * 64 + gc];
                float m00 = fmaxf(v00 + a0.x * di0, 0.0f);
                float m01 = fmaxf(v01 + a0.y * di0, 0.0f);
                float m10 = fmaxf(v10 + a1.x * di1, 0.0f);
                float m11 = fmaxf(v11 + a1.y * di1, 0.0f);
                *(__half2*)&g_Mh[(size_t)row0 * 64 + gc] = __floats2half2_rn(m00, m01);
                *(__half2*)&g_Mh[(size_t)row1 * 64 + gc] = __floats2half2_rn(m10, m11);
                *(float2*)&g_agg[(size_t)row0 * 64 + gc] = make_float2(0.0f, 0.0f);
                *(float2*)&g_agg[(size_t)row1 * 64 + gc] = make_float2(0.0f, 0.0f);
            } else {
                *(float2*)&g_gh[(size_t)row0 * 192 + gc - 64] = make_float2(v00, v01);
                *(float2*)&g_gh[(size_t)row1 * 192 + gc - 64] = make_float2(v10, v11);
            }
        }
    }
}

// ---------------- gemmB: m_fp16 @ wih^T (K=64, N=192 padded to 256) ----------------
__global__ void __launch_bounds__(256) k_gemmB() {
    __shared__ __half As[128][72];
    __shared__ __half Bs[64][136];
    __shared__ float biass[128];
    int tid = threadIdx.x, lane = tid & 31, wid = tid >> 5;
    int warp_m = wid & 3, warp_n = wid >> 2;
    int bn = blockIdx.x * 128, bm = blockIdx.y * 128;

    if (tid < 128) biass[tid] = g_biasB[bn + tid];

    {
        int ar = tid >> 3, ac = (tid & 7) * 8;
#pragma unroll
        for (int p = 0; p < 4; p++) {
            unsigned d = smem_u32(&As[ar + p * 32][ac]);
            asm volatile("cp.async.cg.shared.global [%0], [%1], 16;\n" :: "r"(d),
                         "l"(g_Mh + (size_t)(bm + ar + p * 32) * 64 + ac));
        }
        int br = tid >> 4, bc = (tid & 15) * 8;
#pragma unroll
        for (int p = 0; p < 4; p++) {
            unsigned d = smem_u32(&Bs[br + p * 16][bc]);
            asm volatile("cp.async.cg.shared.global [%0], [%1], 16;\n" :: "r"(d),
                         "l"(g_WihP + (size_t)(br + p * 16) * 256 + bn + bc));
        }
        asm volatile("cp.async.commit_group;\ncp.async.wait_group 0;\n" ::: "memory");
    }
    __syncthreads();

    float acc[2][8][4];
#pragma unroll
    for (int i = 0; i < 2; i++)
#pragma unroll
        for (int j = 0; j < 8; j++)
#pragma unroll
            for (int r = 0; r < 4; r++) acc[i][j][r] = 0.0f;

#pragma unroll
    for (int ks = 0; ks < 4; ks++) {
        unsigned a[2][4];
#pragma unroll
        for (int mt = 0; mt < 2; mt++) {
            unsigned addr = smem_u32(&As[warp_m * 32 + mt * 16 + (lane & 15)]
                                        [ks * 16 + (lane >> 4) * 8]);
            asm volatile("ldmatrix.sync.aligned.m8n8.x4.shared.b16 {%0,%1,%2,%3}, [%4];\n"
                         : "=r"(a[mt][0]), "=r"(a[mt][1]), "=r"(a[mt][2]), "=r"(a[mt][3])
                         : "r"(addr));
        }
        unsigned b[4][4];
#pragma unroll
        for (int p = 0; p < 4; p++) {
            unsigned addr = smem_u32(&Bs[ks * 16 + (lane & 15)]
                                        [warp_n * 64 + p * 16 + (lane >> 4) * 8]);
            asm volatile("ldmatrix.sync.aligned.m8n8.x4.trans.shared.b16 {%0,%1,%2,%3}, [%4];\n"
                         : "=r"(b[p][0]), "=r"(b[p][1]), "=r"(b[p][2]), "=r"(b[p][3])
                         : "r"(addr));
        }
#pragma unroll
        for (int mt = 0; mt < 2; mt++)
#pragma unroll
            for (int nt = 0; nt < 8; nt++) {
                unsigned b0 = b[nt >> 1][(nt & 1) * 2];
                unsigned b1 = b[nt >> 1][(nt & 1) * 2 + 1];
                asm volatile(
                    "mma.sync.aligned.m16n8k16.row.col.f32.f16.f16.f32 "
                    "{%0,%1,%2,%3}, {%4,%5,%6,%7}, {%8,%9}, {%0,%1,%2,%3};\n"
                    : "+f"(acc[mt][nt][0]), "+f"(acc[mt][nt][1]),
                      "+f"(acc[mt][nt][2]), "+f"(acc[mt][nt][3])
                    : "r"(a[mt][0]), "r"(a[mt][1]), "r"(a[mt][2]), "r"(a[mt][3]),
                      "r"(b0), "r"(b1));
            }
    }

    if (bn == 128 && warp_n == 1) return;    // cols 192..255 are padding
#pragma unroll
    for (int mt = 0; mt < 2; mt++) {
        int row0 = bm + warp_m * 32 + mt * 16 + (lane >> 2);
        int row1 = row0 + 8;
#pragma unroll
        for (int nt = 0; nt < 8; nt++) {
            int colL = warp_n * 64 + nt * 8 + (lane & 3) * 2;
            int gc = bn + colL;
            float b0 = biass[colL], b1 = biass[colL + 1];
            *(float2*)&g_gi[(size_t)row0 * 192 + gc] =
                make_float2(acc[mt][nt][0] + b0, acc[mt][nt][1] + b1);
            *(float2*)&g_gi[(size_t)row1 * 192 + gc] =
                make_float2(acc[mt][nt][2] + b0, acc[mt][nt][3] + b1);
        }
    }
}

// ---------------- GRU gates combine ----------------
__global__ void __launch_bounds__(256) k_gru() {
    int idx = blockIdx.x * 256 + threadIdx.x;       // over NN*32
    int n = idx >> 5, dp = (idx & 31) * 2;
    size_t gbase = (size_t)n * 192 + dp;
    float2 gir = *(float2*)&g_gi[gbase];
    float2 giz = *(float2*)&g_gi[gbase + 64];
    float2 gin = *(float2*)&g_gi[gbase + 128];
    float2 ghr = *(float2*)&g_gh[gbase];
    float2 ghz = *(float2*)&g_gh[gbase + 64];
    float2 ghn = *(float2*)&g_gh[gbase + 128];
    float2 h = *(float2*)&g_out[(size_t)n * 64 + dp];
    float r0 = sigm(gir.x + ghr.x), r1 = sigm(gir.y + ghr.y);
    float z0 = sigm(giz.x + ghz.x), z1 = sigm(giz.y + ghz.y);
    float nv0 = tanhf(gin.x + r0 * ghn.x), nv1 = tanhf(gin.y + r1 * ghn.y);
    float h0 = (1.0f - z0) * nv0 + z0 * h.x;
    float h1 = (1.0f - z1) * nv1 + z1 * h.y;
    *(float2*)&g_out[(size_t)n * 64 + dp] = make_float2(h0, h1);
    *(__half2*)&g_outh[(size_t)n * 64 + dp] = __floats2half2_rn(h0, h1);
}

// ---------------- Set2Set + head ----------------
__global__ void __launch_bounds__(256) k_s2s(const float* __restrict__ wih,
                                             const float* __restrict__ whh,
                                             const float* __restrict__ bih,
                                             const float* __restrict__ bhh,
                                             const float* __restrict__ l1w,
                                             const float* __restrict__ l1b,
                                             const float* __restrict__ l2w,
                                             const float* __restrict__ l2b,
                                             float* __restrict__ y) {
    int g = blockIdx.x, tid = threadIdx.x;
    __shared__ float qstar[128], hl[64], cl[64], gsm[256], a_sm[256], red[256], rvp[256];
    __shared__ float s_inv;
    if (tid < 128) qstar[tid] = 0.0f;
    if (tid < 64) { hl[tid] = 0.0f; cl[tid] = 0.0f; }
    int start = g_ptr[g], cnt = g_ptr[g + 1] - start;
    __syncthreads();
    int d = tid & 63, gq = tid >> 6;

    for (int step = 0; step < 3; step++) {
        float acc = bih[tid] + bhh[tid];
        const float* wr = wih + tid * 128;
#pragma unroll 8
        for (int i = 0; i < 128; i++) acc += qstar[i] * wr[i];
        const float* ur = whh + tid * 64;
#pragma unroll 8
        for (int i = 0; i < 64; i++) acc += hl[i] * ur[i];
        gsm[tid] = acc;
        __syncthreads();
        if (tid < 64) {
            float ii = sigm(gsm[tid]);
            float ff = sigm(gsm[64 + tid]);
            float gg = tanhf(gsm[128 + tid]);
            float oo = sigm(gsm[192 + tid]);
            float c = ff * cl[tid] + ii * gg;
            cl[tid] = c;
            hl[tid] = oo * tanhf(c);
        }
        __syncthreads();

        float lmax = -3.0e38f;
        for (int j = tid; j < cnt; j += 256) {
            const float* orow = g_out + (size_t)(start + j) * 64;
            float e = 0.0f;
#pragma unroll 8
            for (int k2 = 0; k2 < 64; k2++) e += orow[k2] * hl[k2];
            lmax = fmaxf(lmax, e);
        }
        red[tid] = lmax;
        __syncthreads();
        for (int s = 128; s; s >>= 1) { if (tid < s) red[tid] = fmaxf(red[tid], red[tid + s]); __syncthreads(); }
        float emax = red[0];
        __syncthreads();

        float rv = 0.0f, asum = 0.0f;
        for (int base = 0; base < cnt; base += 256) {
            int chunk = min(256, cnt - base);
            if (tid < chunk) {
                const float* orow = g_out + (size_t)(start + base + tid) * 64;
                float e = 0.0f;
#pragma unroll 8
                for (int k2 = 0; k2 < 64; k2++) e += orow[k2] * hl[k2];
                a_sm[tid] = expf(e - emax);
            }
            __syncthreads();
            for (int j = gq; j < chunk; j += 4) {
                float a = a_sm[j];
                rv += a * g_out[(size_t)(start + base + j) * 64 + d];
                if (d == 0) asum += a;
            }
            __syncthreads();
        }
        rvp[tid] = rv;
        red[tid] = (d == 0) ? asum : 0.0f;
        __syncthreads();
        if (tid == 0) s_inv = 1.0f / (red[0] + red[64] + red[128] + red[192] + 1e-16f);
        __syncthreads();
        if (tid < 64) {
            float rvt = rvp[tid] + rvp[64 + tid] + rvp[128 + tid] + rvp[192 + tid];
            qstar[tid] = hl[tid];
            qstar[64 + tid] = rvt * s_inv;
        }
        __syncthreads();
    }

    float t = 0.0f;
    if (tid < 64) {
        float acc = l1b[tid];
#pragma unroll 8
        for (int i = 0; i < 128; i++) acc += qstar[i] * l1w[i * 64 + tid];
        t = fmaxf(acc, 0.0f) * l2w[tid];
    }
    red[tid] = (tid < 64) ? t : 0.0f;
    __syncthreads();
    for (int s = 128; s; s >>= 1) { if (tid < s) red[tid] += red[tid + s]; __syncthreads(); }
    if (tid == 0) y[g] = red[0] + l2b[0];
}

// ---------------- host launcher ----------------
extern "C" void kernel_launch(void* const* d_in, const int* in_sizes, int n_in,
                              void* d_out, int out_size) {
    const float* x        = (const float*)d_in[0];
    const int*   ei       = (const int*)  d_in[1];
    const float* ea       = (const float*)d_in[2];
    const int*   batch    = (const int*)  d_in[3];
    const float* lin0_w   = (const float*)d_in[4];
    const float* lin0_b   = (const float*)d_in[5];
    const float* nn_w1    = (const float*)d_in[6];
    const float* nn_b1    = (const float*)d_in[7];
    const float* nn_w2    = (const float*)d_in[8];
    const float* nn_b2    = (const float*)d_in[9];
    const float* conv_root= (const float*)d_in[10];
    const float* conv_bias= (const float*)d_in[11];
    const float* gru_wih  = (const float*)d_in[12];
    const float* gru_whh  = (const float*)d_in[13];
    const float* gru_bih  = (const float*)d_in[14];
    const float* gru_bhh  = (const float*)d_in[15];
    const float* lstm_wih = (const float*)d_in[16];
    const float* lstm_whh = (const float*)d_in[17];
    const float* lstm_bih = (const float*)d_in[18];
    const float* lstm_bhh = (const float*)d_in[19];
    const float* lin1_w   = (const float*)d_in[20];
    const float* lin1_b   = (const float*)d_in[21];
    const float* lin2_w   = (const float*)d_in[22];
    const float* lin2_b   = (const float*)d_in[23];
    float* y = (float*)d_out;

    const int* src  = ei;
    const int* dstv = ei + EE;

    const int GEMM_SMEM = 57344;
    cudaFuncSetAttribute(k_gemm_f16, cudaFuncAttributeMaxDynamicSharedMemorySize, GEMM_SMEM);

    k_pre<<<EE / 2 + 1024, 256>>>(ea, nn_w1, nn_b1, nn_w2);
    k_gemm_f16<<<dim3(32, 256), 256, GEMM_SMEM>>>(nn_b2);
    k_lin0<<<NN / 4, 256>>>(x, lin0_w, lin0_b);

    k_msg<<<EE / 8, 256>>>(src, dstv);                 // iteration 0 message (slot 4)
    k_deg<<<EE / 256, 256>>>(dstv);
    k_ptr<<<3, 256>>>(batch);
    k_pack<<<64, 256>>>(conv_root, gru_whh, gru_wih, conv_bias, gru_bhh, gru_bih);
    k_gemmA<<<dim3(2, 128), 256>>>();
    k_gemmB<<<dim3(2, 128), 256>>>();
    k_gru<<<NN * 32 / 256, 256>>>();

    for (int it = 1; it < 6; it++) {
        k_msg<<<EE / 8, 256>>>(src, dstv);
        k_gemmA<<<dim3(2, 128), 256>>>();
        k_gemmB<<<dim3(2, 128), 256>>>();
        k_gru<<<NN * 32 / 256, 256>>>();
    }

    k_s2s<<<NGR, 256>>>(lstm_wih, lstm_whh, lstm_bih, lstm_bhh,
                        lin1_w, lin1_b, lin2_w, lin2_b, y);
}